// round 3
// baseline (speedup 1.0000x reference)
#include <cuda_runtime.h>
#include <cstdint>
#include <math.h>

// ----------------------------------------------------------------------------
// Problem constants
//   B=16, Nf=1024, Nh=1024, Ng=2048, H=256, L=4 (2 encoders x 2 sublayers)
// ----------------------------------------------------------------------------
#define HDIM 256

// ----------------------------------------------------------------------------
// Scratch (device globals — allocation-free rule)
// ----------------------------------------------------------------------------
__device__ float g_t0  [16 * 2048 * 256];      // proj ping
__device__ float g_t1  [16 * 2048 * 256];      // proj pong
__device__ float g_q   [16 * 1024 * 256];
__device__ float g_k   [16 * 2048 * 256];
__device__ float g_v   [16 * 2048 * 256];
__device__ float g_s   [16L * 1024 * 2048];    // scores / weights (128 MB)
__device__ float g_attn[16 * 1024 * 256];
__device__ float g_xA  [16 * 1024 * 256];
__device__ float g_xB  [16 * 1024 * 256];
__device__ int   g_mtype_hf;                   // 0=int32, 1=uint8, 2=float32
__device__ int   g_mtype_fg;

// ----------------------------------------------------------------------------
// Mask dtype detection. The reference produces bool masks; the harness promotes
// them to an unknown concrete dtype. Classify on-device (deterministic,
// graph-capturable):
//   int32  -> every 4-byte word is 0 or 1
//   uint8  -> every byte is 0 or 1, but some packed word > 1
//   float32-> words are 0 or 0x3f800000
// Scan the first n_words (safe for all encodings: n_words <= n_elems/4).
// ----------------------------------------------------------------------------
__global__ void detect_mask_kernel(const uint32_t* __restrict__ m,
                                   int n_words, int* __restrict__ flag_out)
{
    __shared__ int word_gt1;     // some word not in {0,1}
    __shared__ int byte_bad;     // some byte not in {0,1}
    if (threadIdx.x == 0) { word_gt1 = 0; byte_bad = 0; }
    __syncthreads();

    int lw = 0, lb = 0;
    for (int i = threadIdx.x; i < n_words; i += blockDim.x) {
        uint32_t w = m[i];
        if (w > 1u) lw = 1;
        #pragma unroll
        for (int b = 0; b < 4; b++) {
            uint32_t byte = (w >> (8 * b)) & 0xFFu;
            if (byte > 1u) lb = 1;
        }
    }
    if (lw) atomicOr(&word_gt1, 1);
    if (lb) atomicOr(&byte_bad, 1);
    __syncthreads();

    if (threadIdx.x == 0) {
        int t;
        if (!word_gt1)      t = 0;   // int32
        else if (!byte_bad) t = 1;   // uint8 (packed bools)
        else                t = 2;   // float32
        *flag_out = t;
    }
}

// ----------------------------------------------------------------------------
// SGEMM: C = alpha * A @ B (+ bias), optional B transposed (A @ B^T).
//   A: [M,K] row-major.  B: NN -> [K,N], NT -> [N,K].  batch via blockIdx.z.
//   Tiles: BM=64, BN=64, BK=32, 128 threads, 8x4 per-thread microtile.
//   All dims used here are multiples of the tile sizes -> no bounds checks.
// ----------------------------------------------------------------------------
template<bool TRANS_B, bool BIAS>
__global__ __launch_bounds__(128)
void sgemm_kernel(const float* __restrict__ A,
                  const float* __restrict__ B,
                  const float* __restrict__ bias,
                  float* __restrict__ C,
                  int M, int N, int K,
                  long long sA, long long sB, long long sC,
                  float alpha)
{
    constexpr int BM = 64, BN = 64, BK = 32;
    __shared__ float As[BK][BM];
    __shared__ float Bs[BK][BN];

    const int bz = blockIdx.z;
    A += (long long)bz * sA;
    B += (long long)bz * sB;
    C += (long long)bz * sC;

    const int m0 = blockIdx.y * BM;
    const int n0 = blockIdx.x * BN;
    const int tid = threadIdx.x;          // 0..127
    const int ty = tid >> 4;              // 0..7  -> 8 rows of threads
    const int tx = tid & 15;              // 0..15 -> 16 cols of threads

    float acc[8][4];
    #pragma unroll
    for (int i = 0; i < 8; i++)
        #pragma unroll
        for (int j = 0; j < 4; j++) acc[i][j] = 0.f;

    for (int k0 = 0; k0 < K; k0 += BK) {
        // ---- load A tile (64x32) transposed into As[k][m] ----
        #pragma unroll
        for (int i = 0; i < 4; i++) {
            int id  = tid + i * 128;          // 0..511
            int row = id >> 3;                // 0..63
            int kv  = id & 7;                 // 0..7 (float4 along k)
            float4 va = *(const float4*)(A + (long long)(m0 + row) * K + k0 + kv * 4);
            As[kv * 4 + 0][row] = va.x;
            As[kv * 4 + 1][row] = va.y;
            As[kv * 4 + 2][row] = va.z;
            As[kv * 4 + 3][row] = va.w;
        }
        // ---- load B tile into Bs[k][n] ----
        if (TRANS_B) {
            // B is [N,K]; tile rows n0..n0+63, cols k0..k0+31
            #pragma unroll
            for (int i = 0; i < 4; i++) {
                int id = tid + i * 128;
                int n  = id >> 3;             // 0..63
                int kv = id & 7;              // 0..7
                float4 vb = *(const float4*)(B + (long long)(n0 + n) * K + k0 + kv * 4);
                Bs[kv * 4 + 0][n] = vb.x;
                Bs[kv * 4 + 1][n] = vb.y;
                Bs[kv * 4 + 2][n] = vb.z;
                Bs[kv * 4 + 3][n] = vb.w;
            }
        } else {
            // B is [K,N]; tile rows k0..k0+31, cols n0..n0+63
            #pragma unroll
            for (int i = 0; i < 4; i++) {
                int id = tid + i * 128;
                int kk = id >> 4;             // 0..31
                int nv = id & 15;             // 0..15
                float4 vb = *(const float4*)(B + (long long)(k0 + kk) * N + n0 + nv * 4);
                *(float4*)&Bs[kk][nv * 4] = vb;
            }
        }
        __syncthreads();

        // ---- compute ----
        #pragma unroll
        for (int kk = 0; kk < BK; kk++) {
            float a[8], b[4];
            #pragma unroll
            for (int i = 0; i < 8; i++) a[i] = As[kk][ty * 8 + i];
            #pragma unroll
            for (int j = 0; j < 4; j++) b[j] = Bs[kk][tx * 4 + j];
            #pragma unroll
            for (int i = 0; i < 8; i++)
                #pragma unroll
                for (int j = 0; j < 4; j++)
                    acc[i][j] += a[i] * b[j];
        }
        __syncthreads();
    }

    // ---- epilogue ----
    float bj[4] = {0.f, 0.f, 0.f, 0.f};
    if (BIAS) {
        #pragma unroll
        for (int j = 0; j < 4; j++) bj[j] = bias[n0 + tx * 4 + j];
    }
    #pragma unroll
    for (int i = 0; i < 8; i++) {
        int m = m0 + ty * 8 + i;
        float4 vv;
        vv.x = acc[i][0] * alpha + bj[0];
        vv.y = acc[i][1] * alpha + bj[1];
        vv.z = acc[i][2] * alpha + bj[2];
        vv.w = acc[i][3] * alpha + bj[3];
        *(float4*)(C + (long long)m * N + n0 + tx * 4) = vv;
    }
}

// ----------------------------------------------------------------------------
// Block reductions (256 threads)
// ----------------------------------------------------------------------------
__device__ __forceinline__ float blk_reduce(float v, bool is_max)
{
    __shared__ float sh[256];
    int t = threadIdx.x;
    sh[t] = v;
    __syncthreads();
    #pragma unroll
    for (int s = 128; s > 0; s >>= 1) {
        if (t < s) sh[t] = is_max ? fmaxf(sh[t], sh[t + s]) : (sh[t] + sh[t + s]);
        __syncthreads();
    }
    float r = sh[0];
    __syncthreads();
    return r;
}

// ----------------------------------------------------------------------------
// Masked softmax over rows of S [B*Nq, Nk]. Mask dtype chosen by *mtype.
// NIT = Nk/256 (4 or 8). Row data held in registers between passes.
// ----------------------------------------------------------------------------
template<int NIT>
__global__ __launch_bounds__(256)
void softmax_mask_kernel(float* __restrict__ S, const void* __restrict__ mask,
                         const int* __restrict__ mtype_ptr, int Nk)
{
    const long long row = blockIdx.x;
    float* s = S + row * (long long)Nk;
    const long long mbase = row * (long long)Nk;
    const int t = threadIdx.x;
    const int mtype = *mtype_ptr;   // uniform across grid

    float e[NIT];
    float mx = -INFINITY;
    #pragma unroll
    for (int i = 0; i < NIT; i++) {
        int idx = t + i * 256;
        float v = s[idx];
        bool masked;
        if (mtype == 0)      masked = ((const int*)    mask)[mbase + idx] != 0;
        else if (mtype == 1) masked = ((const uint8_t*)mask)[mbase + idx] != 0;
        else                 masked = ((const float*)  mask)[mbase + idx] != 0.f;
        e[i] = masked ? -INFINITY : v;
        mx = fmaxf(mx, e[i]);
    }
    mx = blk_reduce(mx, true);

    float sum = 0.f;
    #pragma unroll
    for (int i = 0; i < NIT; i++) {
        float ev = (e[i] == -INFINITY) ? 0.f : __expf(e[i] - mx);
        e[i] = ev;
        sum += ev;
    }
    sum = blk_reduce(sum, false);
    float inv = (sum > 0.f) ? (1.f / sum) : 0.f;

    #pragma unroll
    for (int i = 0; i < NIT; i++)
        s[t + i * 256] = e[i] * inv;
}

// ----------------------------------------------------------------------------
// LayerNorm(H=256) * gamma + beta + residual. One block (256 thr) per row.
// ----------------------------------------------------------------------------
__global__ __launch_bounds__(256)
void ln_res_kernel(const float* __restrict__ x, const float* __restrict__ res,
                   const float* __restrict__ gamma, const float* __restrict__ beta,
                   float* __restrict__ out)
{
    const long long row = blockIdx.x;
    const int t = threadIdx.x;
    float v = x[row * HDIM + t];
    float mu = blk_reduce(v, false) * (1.f / HDIM);
    float d = v - mu;
    float var = blk_reduce(d * d, false) * (1.f / HDIM);
    float ln = d * rsqrtf(var + 1e-5f) * gamma[t] + beta[t];
    out[row * HDIM + t] = ln + res[row * HDIM + t];
}

__global__ void add_kernel(const float* __restrict__ a, const float* __restrict__ b,
                           float* __restrict__ o, long long n)
{
    long long i = (long long)blockIdx.x * blockDim.x + threadIdx.x;
    if (i < n) o[i] = a[i] + b[i];
}

// ----------------------------------------------------------------------------
// Host orchestration
// ----------------------------------------------------------------------------
static void proj3(const float* x, int M, const float* W, const float* b,
                  float* outp, float* t0, float* t1)
{
    // 3 chained [M,256] @ [256,256] + bias
    dim3 g(HDIM / 64, M / 64, 1);
    sgemm_kernel<false, true><<<g, 128>>>(x,  W + 0 * 65536, b + 0 * 256, t0,
                                          M, HDIM, HDIM, 0, 0, 0, 1.f);
    sgemm_kernel<false, true><<<g, 128>>>(t0, W + 1 * 65536, b + 1 * 256, t1,
                                          M, HDIM, HDIM, 0, 0, 0, 1.f);
    sgemm_kernel<false, true><<<g, 128>>>(t1, W + 2 * 65536, b + 2 * 256, outp,
                                          M, HDIM, HDIM, 0, 0, 0, 1.f);
}

static void run_layer(const float* x1, const float* x2, const void* mask,
                      const int* mtype_ptr, int Nk,
                      const float* Wq_l, const float* bq_l,
                      const float* Wk_l, const float* bk_l,
                      const float* Wv_l, const float* bv_l,
                      const float* gamma_l, const float* beta_l,
                      float* xout,
                      float* t0, float* t1, float* q, float* k, float* v,
                      float* s, float* attn)
{
    const int Bb = 16, Nq = 1024;
    const int Mq = Bb * Nq;
    const int Mk = Bb * Nk;

    proj3(x1, Mq, Wq_l, bq_l, q, t0, t1);
    proj3(x2, Mk, Wk_l, bk_l, k, t0, t1);
    proj3(x2, Mk, Wv_l, bv_l, v, t0, t1);

    // scores: S[b] = Q[b] @ K[b]^T * (1/16)
    {
        dim3 g(Nk / 64, Nq / 64, Bb);
        sgemm_kernel<true, false><<<g, 128>>>(q, k, nullptr, s,
            Nq, Nk, HDIM,
            (long long)Nq * HDIM, (long long)Nk * HDIM, (long long)Nq * Nk,
            0.0625f);
    }

    // masked softmax
    if (Nk == 1024) softmax_mask_kernel<4><<<Bb * Nq, 256>>>(s, mask, mtype_ptr, Nk);
    else            softmax_mask_kernel<8><<<Bb * Nq, 256>>>(s, mask, mtype_ptr, Nk);

    // attn out: X[b] = S[b] @ V[b]
    {
        dim3 g(HDIM / 64, Nq / 64, Bb);
        sgemm_kernel<false, false><<<g, 128>>>(s, v, nullptr, attn,
            Nq, HDIM, Nk,
            (long long)Nq * Nk, (long long)Nk * HDIM, (long long)Nq * HDIM,
            1.0f);
    }

    // LN + residual
    ln_res_kernel<<<Bb * Nq, 256>>>(attn, x1, gamma_l, beta_l, xout);
}

extern "C" void kernel_launch(void* const* d_in, const int* in_sizes, int n_in,
                              void* d_out, int out_size)
{
    const float* future  = (const float*)d_in[0];
    const float* history = (const float*)d_in[1];
    const float* graph   = (const float*)d_in[2];
    const void*  mask_hf = d_in[3];
    const void*  mask_fg = d_in[4];
    const float* Wq      = (const float*)d_in[5];
    const float* bq      = (const float*)d_in[6];
    const float* Wk      = (const float*)d_in[7];
    const float* bk      = (const float*)d_in[8];
    const float* Wv      = (const float*)d_in[9];
    const float* bv      = (const float*)d_in[10];
    const float* gamma   = (const float*)d_in[11];
    const float* beta    = (const float*)d_in[12];
    float* out = (float*)d_out;

    float *t0, *t1, *q, *k, *v, *s, *attn, *xA, *xB;
    int *mt_hf, *mt_fg;
    cudaGetSymbolAddress((void**)&t0,    g_t0);
    cudaGetSymbolAddress((void**)&t1,    g_t1);
    cudaGetSymbolAddress((void**)&q,     g_q);
    cudaGetSymbolAddress((void**)&k,     g_k);
    cudaGetSymbolAddress((void**)&v,     g_v);
    cudaGetSymbolAddress((void**)&s,     g_s);
    cudaGetSymbolAddress((void**)&attn,  g_attn);
    cudaGetSymbolAddress((void**)&xA,    g_xA);
    cudaGetSymbolAddress((void**)&xB,    g_xB);
    cudaGetSymbolAddress((void**)&mt_hf, g_mtype_hf);
    cudaGetSymbolAddress((void**)&mt_fg, g_mtype_fg);

    // Detect mask dtypes (safe word count: n_elems/4 words valid in all encodings)
    {
        int nw_hf = in_sizes[3] / 4; if (nw_hf > 65536) nw_hf = 65536;
        int nw_fg = in_sizes[4] / 4; if (nw_fg > 65536) nw_fg = 65536;
        detect_mask_kernel<<<1, 256>>>((const uint32_t*)mask_hf, nw_hf, mt_hf);
        detect_mask_kernel<<<1, 256>>>((const uint32_t*)mask_fg, nw_fg, mt_fg);
    }

    const long long WL = 3LL * 65536;   // weight stride per layer
    const long long BL = 3LL * 256;     // bias stride per layer

    // encoder 1: cross(x, history), layers 0..1
    run_layer(future, history, mask_hf, mt_hf, 1024,
              Wq + 0 * WL, bq + 0 * BL, Wk + 0 * WL, bk + 0 * BL, Wv + 0 * WL, bv + 0 * BL,
              gamma + 0 * 256, beta + 0 * 256,
              xA, t0, t1, q, k, v, s, attn);
    run_layer(xA, history, mask_hf, mt_hf, 1024,
              Wq + 1 * WL, bq + 1 * BL, Wk + 1 * WL, bk + 1 * BL, Wv + 1 * WL, bv + 1 * BL,
              gamma + 1 * 256, beta + 1 * 256,
              xB, t0, t1, q, k, v, s, attn);
    // encoder 2: cross(x, graph), layers 2..3
    run_layer(xB, graph, mask_fg, mt_fg, 2048,
              Wq + 2 * WL, bq + 2 * BL, Wk + 2 * WL, bk + 2 * BL, Wv + 2 * WL, bv + 2 * BL,
              gamma + 2 * 256, beta + 2 * 256,
              xA, t0, t1, q, k, v, s, attn);
    run_layer(xA, graph, mask_fg, mt_fg, 2048,
              Wq + 3 * WL, bq + 3 * BL, Wk + 3 * WL, bk + 3 * BL, Wv + 3 * WL, bv + 3 * BL,
              gamma + 3 * 256, beta + 3 * 256,
              xB, t0, t1, q, k, v, s, attn);

    // out = future + x
    long long n = (long long)out_size;
    add_kernel<<<(unsigned)((n + 255) / 256), 256>>>(future, xB, out, n);
}

// round 6
// speedup vs baseline: 1.9775x; 1.9775x over previous
// bf16-split mma.sync (HMMA) implementation of CrossEncoder4FutureTrajectory.
#include <cuda_runtime.h>
#include <cuda_bf16.h>
#include <cstdint>
#include <math.h>

#define HDIM 256
typedef __nv_bfloat16 bf16;

// ---------------- scratch (device globals) ----------------
__device__ float g_t0[16*2048*256];
__device__ float g_t1[16*2048*256];
__device__ float g_q [16*1024*256];
__device__ float g_k [16*2048*256];
__device__ float g_v [16*2048*256];
__device__ float g_vt[16*2048*256];
__device__ float g_s [16LL*1024*2048];
__device__ float g_at[16*1024*256];
__device__ float g_xA[16*1024*256];
__device__ float g_xB[16*1024*256];
__device__ float g_wqT[12*65536];
__device__ float g_wkT[12*65536];
__device__ float g_wvT[12*65536];
__device__ int g_mt_hf, g_mt_fg;

// ---------------- helpers ----------------
__device__ __forceinline__ uint32_t smem_u32(const void* p){
    uint32_t a; asm("{ .reg .u64 t; cvta.to.shared.u64 t, %1; cvt.u32.u64 %0, t; }":"=r"(a):"l"(p)); return a;
}
__device__ __forceinline__ void ldsm4(uint32_t addr, uint32_t* r){
    asm volatile("ldmatrix.sync.aligned.m8n8.x4.shared.b16 {%0,%1,%2,%3}, [%4];"
        : "=r"(r[0]),"=r"(r[1]),"=r"(r[2]),"=r"(r[3]) : "r"(addr));
}
__device__ __forceinline__ void mma16816(float* c, const uint32_t* a, const uint32_t* b){
    asm volatile("mma.sync.aligned.m16n8k16.row.col.f32.bf16.bf16.f32 "
        "{%0,%1,%2,%3},{%4,%5,%6,%7},{%8,%9},{%0,%1,%2,%3};"
        : "+f"(c[0]),"+f"(c[1]),"+f"(c[2]),"+f"(c[3])
        : "r"(a[0]),"r"(a[1]),"r"(a[2]),"r"(a[3]),"r"(b[0]),"r"(b[1]));
}
__device__ __forceinline__ void split4(float4 v, uint2& h, uint2& l){
    bf16 hb[4], lb[4];
    float xs[4] = {v.x, v.y, v.z, v.w};
    #pragma unroll
    for (int i=0;i<4;i++){ hb[i]=__float2bfloat16(xs[i]); lb[i]=__float2bfloat16(xs[i]-__bfloat162float(hb[i])); }
    h = *(uint2*)hb; l = *(uint2*)lb;
}

// ============================================================================
// NT GEMM via mma.sync: C = alpha*(A @ B^T) (+bias).
// A [M,K], B [N,K] fp32 row-major, batch via blockIdx.z.
// CTA tile 128x128, K-chunk 32. 512 threads = 16 warps (4x4), warp tile 32x32.
// smem: Ah/Al/Bh/Bl each [128][40] bf16 (80B row stride -> ldmatrix conflict-free).
// ============================================================================
#define SST 40   // smem row stride in bf16 units

template<bool BIAS>
__global__ __launch_bounds__(512)
void gemm_mma(const float* __restrict__ A, const float* __restrict__ B,
              const float* __restrict__ bias, float* __restrict__ C,
              int N, int K, long long szA, long long szB, long long szC, float alpha)
{
    __shared__ bf16 sAh[128*SST], sAl[128*SST], sBh[128*SST], sBl[128*SST];
    const int tid = threadIdx.x, warp = tid>>5, lane = tid&31;
    const int wm = warp>>2, wn = warp&3;          // 4x4 warp grid
    const int m0 = blockIdx.y*128, n0 = blockIdx.x*128, z = blockIdx.z;
    A += (long long)z*szA; B += (long long)z*szB;

    const uint32_t bAh = smem_u32(sAh), bAl = smem_u32(sAl);
    const uint32_t bBh = smem_u32(sBh), bBl = smem_u32(sBl);

    float acc[2][4][4];
    #pragma unroll
    for (int i=0;i<2;i++)
        #pragma unroll
        for (int j=0;j<4;j++)
            #pragma unroll
            for (int t=0;t<4;t++) acc[i][j][t] = 0.f;

    const int nch = K >> 5;
    for (int kc=0; kc<nch; kc++){
        const int k0 = kc<<5;
        // fill smem: 128 rows x 32 fp32 for A and B, split to bf16 hi/lo
        #pragma unroll
        for (int i=0;i<2;i++){
            int id = tid + (i<<9);                 // 0..1023
            int r = id>>3, c4 = id&7;
            uint2 h, l;
            split4(*(const float4*)(A + (long long)(m0+r)*K + k0 + c4*4), h, l);
            *(uint2*)(sAh + r*SST + c4*4) = h;
            *(uint2*)(sAl + r*SST + c4*4) = l;
            split4(*(const float4*)(B + (long long)(n0+r)*K + k0 + c4*4), h, l);
            *(uint2*)(sBh + r*SST + c4*4) = h;
            *(uint2*)(sBl + r*SST + c4*4) = l;
        }
        __syncthreads();

        #pragma unroll
        for (int k16=0; k16<2; k16++){
            const uint32_t akoff = k16*32 + ((lane>>4)<<4);
            const uint32_t bkoff = k16*32 + (((lane>>3)&1)<<4);
            const uint32_t arow  = (wm*32 + (lane&15)) * (SST*2);
            const uint32_t brow  = (wn*32 + ((lane>>4)<<3) + (lane&7)) * (SST*2);

            uint32_t Ah[2][4], Al[2][4], Bh[2][4], Bl[2][4];
            #pragma unroll
            for (int mi=0;mi<2;mi++){
                ldsm4(bAh + arow + mi*16*(SST*2) + akoff, Ah[mi]);
                ldsm4(bAl + arow + mi*16*(SST*2) + akoff, Al[mi]);
            }
            #pragma unroll
            for (int bi=0;bi<2;bi++){
                ldsm4(bBh + brow + bi*16*(SST*2) + bkoff, Bh[bi]);
                ldsm4(bBl + brow + bi*16*(SST*2) + bkoff, Bl[bi]);
            }
            #pragma unroll
            for (int mi=0;mi<2;mi++)
                #pragma unroll
                for (int ni=0;ni<4;ni++){
                    mma16816(acc[mi][ni], Ah[mi], &Bh[ni>>1][(ni&1)*2]);   // Ah*Bh
                    mma16816(acc[mi][ni], Ah[mi], &Bl[ni>>1][(ni&1)*2]);   // Ah*Bl
                    mma16816(acc[mi][ni], Al[mi], &Bh[ni>>1][(ni&1)*2]);   // Al*Bh
                }
        }
        __syncthreads();
    }

    // epilogue
    C += (long long)z*szC;
    const int mrow = m0 + wm*32 + (lane>>2);
    const int ncol = n0 + wn*32 + (lane&3)*2;
    #pragma unroll
    for (int mi=0;mi<2;mi++)
        #pragma unroll
        for (int ni=0;ni<4;ni++)
            #pragma unroll
            for (int half=0; half<2; half++){
                int r = mrow + mi*16 + half*8;
                int c = ncol + ni*8;
                float2 v;
                v.x = acc[mi][ni][half*2+0]*alpha;
                v.y = acc[mi][ni][half*2+1]*alpha;
                if (BIAS){ v.x += __ldg(bias+c); v.y += __ldg(bias+c+1); }
                *(float2*)(C + (long long)r*N + c) = v;
            }
}

// ---------------- transpose: out[z][c][r] = in[z][r][c] ----------------
__global__ void transpose_k(const float* __restrict__ in, float* __restrict__ out,
                            int R, int C, long long sIn, long long sOut)
{
    __shared__ float t[32][33];
    const int z = blockIdx.z;
    in += (long long)z*sIn; out += (long long)z*sOut;
    int r0 = blockIdx.y*32, c0 = blockIdx.x*32;
    #pragma unroll
    for (int j=0;j<4;j++)
        t[threadIdx.y+j*8][threadIdx.x] = in[(long long)(r0+threadIdx.y+j*8)*C + c0+threadIdx.x];
    __syncthreads();
    #pragma unroll
    for (int j=0;j<4;j++)
        out[(long long)(c0+threadIdx.y+j*8)*R + r0+threadIdx.x] = t[threadIdx.x][threadIdx.y+j*8];
}

// ---------------- mask dtype detection (0=int32,1=uint8,2=float32) ----------
__global__ void detect_mask_kernel(const uint32_t* __restrict__ m, int nw, int* __restrict__ f)
{
    __shared__ int wg, bb;
    if (threadIdx.x==0){ wg=0; bb=0; }
    __syncthreads();
    int lw=0, lb=0;
    for (int i=threadIdx.x;i<nw;i+=blockDim.x){
        uint32_t w = m[i];
        if (w>1u) lw=1;
        #pragma unroll
        for (int b=0;b<4;b++) if (((w>>(8*b))&0xFFu)>1u) lb=1;
    }
    if (lw) atomicOr(&wg,1);
    if (lb) atomicOr(&bb,1);
    __syncthreads();
    if (threadIdx.x==0) *f = (!wg)?0:((!bb)?1:2);
}

// ---------------- softmax / LN / add ----------------
__device__ __forceinline__ float blk_red(float v, bool mx){
    __shared__ float sh[256];
    int t = threadIdx.x; sh[t]=v; __syncthreads();
    #pragma unroll
    for (int s=128;s>0;s>>=1){ if (t<s) sh[t]= mx?fmaxf(sh[t],sh[t+s]):(sh[t]+sh[t+s]); __syncthreads(); }
    float r = sh[0]; __syncthreads(); return r;
}

template<int NIT>
__global__ __launch_bounds__(256)
void softmax_mask_kernel(float* __restrict__ S, const void* __restrict__ mask,
                         const int* __restrict__ mt_p, int Nk)
{
    const long long row = blockIdx.x;
    float* s = S + row*(long long)Nk;
    const long long mb = row*(long long)Nk;
    const int t = threadIdx.x, mt = *mt_p;
    float e[NIT]; float mx = -INFINITY;
    #pragma unroll
    for (int i=0;i<NIT;i++){
        int idx = t + i*256;
        float v = s[idx]; bool msk;
        if (mt==0)      msk = ((const int*)mask)[mb+idx]!=0;
        else if (mt==1) msk = ((const uint8_t*)mask)[mb+idx]!=0;
        else            msk = ((const float*)mask)[mb+idx]!=0.f;
        e[i] = msk ? -INFINITY : v;
        mx = fmaxf(mx, e[i]);
    }
    mx = blk_red(mx, true);
    float sum = 0.f;
    #pragma unroll
    for (int i=0;i<NIT;i++){ float ev = (e[i]==-INFINITY)?0.f:__expf(e[i]-mx); e[i]=ev; sum+=ev; }
    sum = blk_red(sum, false);
    float inv = (sum>0.f)?(1.f/sum):0.f;
    #pragma unroll
    for (int i=0;i<NIT;i++) s[t+i*256] = e[i]*inv;
}

__global__ __launch_bounds__(256)
void ln_res_kernel(const float* __restrict__ x, const float* __restrict__ res,
                   const float* __restrict__ gm, const float* __restrict__ bt,
                   float* __restrict__ out)
{
    const long long row = blockIdx.x;
    const int t = threadIdx.x;
    float v = x[row*HDIM+t];
    float mu = blk_red(v,false)*(1.f/HDIM);
    float d = v-mu;
    float var = blk_red(d*d,false)*(1.f/HDIM);
    out[row*HDIM+t] = d*rsqrtf(var+1e-5f)*gm[t]+bt[t] + res[row*HDIM+t];
}

__global__ void add_kernel(const float* __restrict__ a, const float* __restrict__ b,
                           float* __restrict__ o, long long n)
{
    long long i = (long long)blockIdx.x*blockDim.x + threadIdx.x;
    if (i<n) o[i] = a[i]+b[i];
}

// ---------------- host orchestration ----------------
static void gemm(const float* A, const float* B, const float* bias, float* C,
                 int M, int N, int K, long long sA, long long sB, long long sC,
                 float alpha, int nz)
{
    dim3 g(N/128, M/128, nz);
    if (bias) gemm_mma<true ><<<g, 512>>>(A,B,bias,C,N,K,sA,sB,sC,alpha);
    else      gemm_mma<false><<<g, 512>>>(A,B,nullptr,C,N,K,sA,sB,sC,alpha);
}

static void proj3(const float* x, int M, const float* wT, const float* b,
                  float* outp, float* t0, float* t1)
{
    gemm(x,  wT+0*65536, b+0*256, t0,   M,256,256, 0,0,0, 1.f, 1);
    gemm(t0, wT+1*65536, b+1*256, t1,   M,256,256, 0,0,0, 1.f, 1);
    gemm(t1, wT+2*65536, b+2*256, outp, M,256,256, 0,0,0, 1.f, 1);
}

static void run_layer(const float* x1, const float* x2, const void* mask,
                      const int* mt, int Nk,
                      const float* wqT, const float* bq_l,
                      const float* wkT, const float* bk_l,
                      const float* wvT, const float* bv_l,
                      const float* gm, const float* bt, float* xout,
                      float* t0, float* t1, float* q, float* k, float* v,
                      float* vt, float* s, float* at)
{
    const int Bb=16, Nq=1024;
    proj3(x1, Bb*Nq, wqT, bq_l, q, t0, t1);
    proj3(x2, Bb*Nk, wkT, bk_l, k, t0, t1);
    proj3(x2, Bb*Nk, wvT, bv_l, v, t0, t1);
    {   // V^T per batch
        dim3 g(HDIM/32, Nk/32, Bb);
        transpose_k<<<g, dim3(32,8)>>>(v, vt, Nk, HDIM, (long long)Nk*HDIM, (long long)Nk*HDIM);
    }
    // S = Q K^T / 16
    gemm(q, k, nullptr, s, Nq, Nk, HDIM,
         (long long)Nq*HDIM, (long long)Nk*HDIM, (long long)Nq*Nk, 0.0625f, Bb);
    if (Nk==1024) softmax_mask_kernel<4><<<Bb*Nq,256>>>(s, mask, mt, Nk);
    else          softmax_mask_kernel<8><<<Bb*Nq,256>>>(s, mask, mt, Nk);
    // X = S @ V  (NT against V^T)
    gemm(s, vt, nullptr, at, Nq, HDIM, Nk,
         (long long)Nq*Nk, (long long)Nk*HDIM, (long long)Nq*HDIM, 1.f, Bb);
    ln_res_kernel<<<Bb*Nq,256>>>(at, x1, gm, bt, xout);
}

extern "C" void kernel_launch(void* const* d_in, const int* in_sizes, int n_in,
                              void* d_out, int out_size)
{
    const float* future  = (const float*)d_in[0];
    const float* history = (const float*)d_in[1];
    const float* graph   = (const float*)d_in[2];
    const void*  mask_hf = d_in[3];
    const void*  mask_fg = d_in[4];
    const float* Wq = (const float*)d_in[5];
    const float* bq = (const float*)d_in[6];
    const float* Wk = (const float*)d_in[7];
    const float* bk = (const float*)d_in[8];
    const float* Wv = (const float*)d_in[9];
    const float* bv = (const float*)d_in[10];
    const float* gm = (const float*)d_in[11];
    const float* bt = (const float*)d_in[12];
    float* out = (float*)d_out;

    float *t0,*t1,*q,*k,*v,*vt,*s,*at,*xA,*xB,*wqT,*wkT,*wvT;
    int *mhf,*mfg;
    cudaGetSymbolAddress((void**)&t0,g_t0);   cudaGetSymbolAddress((void**)&t1,g_t1);
    cudaGetSymbolAddress((void**)&q,g_q);     cudaGetSymbolAddress((void**)&k,g_k);
    cudaGetSymbolAddress((void**)&v,g_v);     cudaGetSymbolAddress((void**)&vt,g_vt);
    cudaGetSymbolAddress((void**)&s,g_s);     cudaGetSymbolAddress((void**)&at,g_at);
    cudaGetSymbolAddress((void**)&xA,g_xA);   cudaGetSymbolAddress((void**)&xB,g_xB);
    cudaGetSymbolAddress((void**)&wqT,g_wqT); cudaGetSymbolAddress((void**)&wkT,g_wkT);
    cudaGetSymbolAddress((void**)&wvT,g_wvT);
    cudaGetSymbolAddress((void**)&mhf,g_mt_hf); cudaGetSymbolAddress((void**)&mfg,g_mt_fg);

    {
        int nh = in_sizes[3]/4; if (nh>65536) nh=65536;
        int ng = in_sizes[4]/4; if (ng>65536) ng=65536;
        detect_mask_kernel<<<1,256>>>((const uint32_t*)mask_hf, nh, mhf);
        detect_mask_kernel<<<1,256>>>((const uint32_t*)mask_fg, ng, mfg);
    }
    {   // transpose all 12 weight matrices per tensor (layer-major batch)
        dim3 g(8,8,12), b(32,8);
        transpose_k<<<g,b>>>(Wq, wqT, 256,256, 65536,65536);
        transpose_k<<<g,b>>>(Wk, wkT, 256,256, 65536,65536);
        transpose_k<<<g,b>>>(Wv, wvT, 256,256, 65536,65536);
    }

    const long long WL = 3LL*65536, BL = 3LL*256;
    run_layer(future, history, mask_hf, mhf, 1024,
              wqT+0*WL, bq+0*BL, wkT+0*WL, bk+0*BL, wvT+0*WL, bv+0*BL,
              gm+0*256, bt+0*256, xA, t0,t1,q,k,v,vt,s,at);
    run_layer(xA, history, mask_hf, mhf, 1024,
              wqT+1*WL, bq+1*BL, wkT+1*WL, bk+1*BL, wvT+1*WL, bv+1*BL,
              gm+1*256, bt+1*256, xB, t0,t1,q,k,v,vt,s,at);
    run_layer(xB, graph, mask_fg, mfg, 2048,
              wqT+2*WL, bq+2*BL, wkT+2*WL, bk+2*BL, wvT+2*WL, bv+2*BL,
              gm+2*256, bt+2*256, xA, t0,t1,q,k,v,vt,s,at);
    run_layer(xA, graph, mask_fg, mfg, 2048,
              wqT+3*WL, bq+3*BL, wkT+3*WL, bk+3*BL, wvT+3*WL, bv+3*BL,
              gm+3*256, bt+3*256, xB, t0,t1,q,k,v,vt,s,at);

    long long n = (long long)out_size;
    add_kernel<<<(unsigned)((n+255)/256),256>>>(future, xB, out, n);
}

// round 7
// speedup vs baseline: 2.3228x; 1.1746x over previous
// bf16-split mma.sync pipelined implementation of CrossEncoder4FutureTrajectory.
#include <cuda_runtime.h>
#include <cuda_bf16.h>
#include <cstdint>
#include <math.h>

#define HDIM 256
typedef __nv_bfloat16 bf16;

// ---------------- scratch (device globals) ----------------
__device__ float g_t0[16*2048*256];
__device__ float g_t1[16*2048*256];
__device__ float g_q [16*1024*256];
__device__ float g_k [16*2048*256];
__device__ float g_v [16*2048*256];
__device__ float g_vt[16*2048*256];
__device__ float g_s [16LL*1024*2048];
__device__ float g_at[16*1024*256];
__device__ float g_xA[16*1024*256];
__device__ float g_xB[16*1024*256];
__device__ float g_wqT[12*65536];
__device__ float g_wkT[12*65536];
__device__ float g_wvT[12*65536];
__device__ int g_mt_hf, g_mt_fg;

// ---------------- helpers ----------------
__device__ __forceinline__ uint32_t smem_u32(const void* p){
    uint32_t a; asm("{ .reg .u64 t; cvta.to.shared.u64 t, %1; cvt.u32.u64 %0, t; }":"=r"(a):"l"(p)); return a;
}
__device__ __forceinline__ void ldsm4(uint32_t addr, uint32_t* r){
    asm volatile("ldmatrix.sync.aligned.m8n8.x4.shared.b16 {%0,%1,%2,%3}, [%4];"
        : "=r"(r[0]),"=r"(r[1]),"=r"(r[2]),"=r"(r[3]) : "r"(addr));
}
__device__ __forceinline__ void mma16816(float* c, const uint32_t* a, const uint32_t* b){
    asm volatile("mma.sync.aligned.m16n8k16.row.col.f32.bf16.bf16.f32 "
        "{%0,%1,%2,%3},{%4,%5,%6,%7},{%8,%9},{%0,%1,%2,%3};"
        : "+f"(c[0]),"+f"(c[1]),"+f"(c[2]),"+f"(c[3])
        : "r"(a[0]),"r"(a[1]),"r"(a[2]),"r"(a[3]),"r"(b[0]),"r"(b[1]));
}
__device__ __forceinline__ void split4(float4 v, uint2& h, uint2& l){
    bf16 hb[4], lb[4];
    float xs[4] = {v.x, v.y, v.z, v.w};
    #pragma unroll
    for (int i=0;i<4;i++){ hb[i]=__float2bfloat16(xs[i]); lb[i]=__float2bfloat16(xs[i]-__bfloat162float(hb[i])); }
    h = *(uint2*)hb; l = *(uint2*)lb;
}

// ============================================================================
// NT GEMM via mma.sync: C = alpha*(A @ B^T) (+bias).
// A [M,K], B [N,K] fp32 row-major, batch via blockIdx.z.
// CTA tile 128x128, K-chunk 64. 512 threads = 16 warps (4x4), warp tile 32x32.
// smem (dynamic): Ah/Al/Bh/Bl each [128][72] bf16 (144B stride, ldmatrix clean).
// Register double-buffer: next chunk's fp32 LDGs issued before current MMAs.
// ============================================================================
#define SST 72                      // smem row stride (halfwords) for K-chunk 64
#define GSMEM (4*128*SST*2)         // 73728 B

template<bool BIAS>
__global__ __launch_bounds__(512)
void gemm_mma(const float* __restrict__ A, const float* __restrict__ B,
              const float* __restrict__ bias, float* __restrict__ C,
              int N, int K, long long szA, long long szB, long long szC, float alpha)
{
    extern __shared__ bf16 smem[];
    bf16* sAh = smem;
    bf16* sAl = smem + 128*SST;
    bf16* sBh = smem + 2*128*SST;
    bf16* sBl = smem + 3*128*SST;

    const int tid = threadIdx.x, warp = tid>>5, lane = tid&31;
    const int wm = warp>>2, wn = warp&3;          // 4x4 warp grid
    const int m0 = blockIdx.y*128, n0 = blockIdx.x*128, z = blockIdx.z;
    A += (long long)z*szA; B += (long long)z*szB;

    const uint32_t bAh = smem_u32(sAh), bAl = smem_u32(sAl);
    const uint32_t bBh = smem_u32(sBh), bBl = smem_u32(sBl);

    float acc[2][4][4];
    #pragma unroll
    for (int i=0;i<2;i++)
        #pragma unroll
        for (int j=0;j<4;j++)
            #pragma unroll
            for (int t=0;t<4;t++) acc[i][j][t] = 0.f;

    // fill indices: 128 rows x 16 float4 per operand = 2048 f4; 512 thr -> 4 each
    int fr[4], fc[4];
    #pragma unroll
    for (int i=0;i<4;i++){ int id = tid + (i<<9); fr[i]=id>>4; fc[i]=(id&15)<<2; }

    float4 pA[4], pB[4];
    {   // prefetch chunk 0
        #pragma unroll
        for (int i=0;i<4;i++){
            pA[i] = *(const float4*)(A + (long long)(m0+fr[i])*K + fc[i]);
            pB[i] = *(const float4*)(B + (long long)(n0+fr[i])*K + fc[i]);
        }
    }

    const int nch = K >> 6;
    for (int kc=0; kc<nch; kc++){
        // store prefetched chunk to smem (split fp32 -> bf16 hi/lo)
        #pragma unroll
        for (int i=0;i<4;i++){
            uint2 h, l;
            split4(pA[i], h, l);
            *(uint2*)(sAh + fr[i]*SST + fc[i]) = h;
            *(uint2*)(sAl + fr[i]*SST + fc[i]) = l;
            split4(pB[i], h, l);
            *(uint2*)(sBh + fr[i]*SST + fc[i]) = h;
            *(uint2*)(sBl + fr[i]*SST + fc[i]) = l;
        }
        __syncthreads();

        // issue next chunk's gmem loads before MMAs (latency overlap)
        if (kc+1 < nch){
            const int k0 = (kc+1)<<6;
            #pragma unroll
            for (int i=0;i<4;i++){
                pA[i] = *(const float4*)(A + (long long)(m0+fr[i])*K + k0 + fc[i]);
                pB[i] = *(const float4*)(B + (long long)(n0+fr[i])*K + k0 + fc[i]);
            }
        }

        #pragma unroll
        for (int k16=0; k16<4; k16++){
            const uint32_t akoff = k16*32 + ((lane>>4)<<4);
            const uint32_t bkoff = k16*32 + (((lane>>3)&1)<<4);
            const uint32_t arow  = (wm*32 + (lane&15)) * (SST*2);
            const uint32_t brow  = (wn*32 + ((lane>>4)<<3) + (lane&7)) * (SST*2);

            uint32_t Ah[2][4], Al[2][4], Bh[2][4], Bl[2][4];
            #pragma unroll
            for (int mi=0;mi<2;mi++){
                ldsm4(bAh + arow + mi*16*(SST*2) + akoff, Ah[mi]);
                ldsm4(bAl + arow + mi*16*(SST*2) + akoff, Al[mi]);
            }
            #pragma unroll
            for (int bi=0;bi<2;bi++){
                ldsm4(bBh + brow + bi*16*(SST*2) + bkoff, Bh[bi]);
                ldsm4(bBl + brow + bi*16*(SST*2) + bkoff, Bl[bi]);
            }
            #pragma unroll
            for (int mi=0;mi<2;mi++)
                #pragma unroll
                for (int ni=0;ni<4;ni++){
                    mma16816(acc[mi][ni], Ah[mi], &Bh[ni>>1][(ni&1)*2]);   // Ah*Bh
                    mma16816(acc[mi][ni], Ah[mi], &Bl[ni>>1][(ni&1)*2]);   // Ah*Bl
                    mma16816(acc[mi][ni], Al[mi], &Bh[ni>>1][(ni&1)*2]);   // Al*Bh
                }
        }
        __syncthreads();
    }

    // epilogue
    C += (long long)z*szC;
    const int mrow = m0 + wm*32 + (lane>>2);
    const int ncol = n0 + wn*32 + (lane&3)*2;
    #pragma unroll
    for (int mi=0;mi<2;mi++)
        #pragma unroll
        for (int ni=0;ni<4;ni++)
            #pragma unroll
            for (int half=0; half<2; half++){
                int r = mrow + mi*16 + half*8;
                int c = ncol + ni*8;
                float2 v;
                v.x = acc[mi][ni][half*2+0]*alpha;
                v.y = acc[mi][ni][half*2+1]*alpha;
                if (BIAS){ v.x += __ldg(bias+c); v.y += __ldg(bias+c+1); }
                *(float2*)(C + (long long)r*N + c) = v;
            }
}

// ---------------- transpose: out[z][c][r] = in[z][r][c] ----------------
__global__ void transpose_k(const float* __restrict__ in, float* __restrict__ out,
                            int R, int C, long long sIn, long long sOut)
{
    __shared__ float t[32][33];
    const int z = blockIdx.z;
    in += (long long)z*sIn; out += (long long)z*sOut;
    int r0 = blockIdx.y*32, c0 = blockIdx.x*32;
    #pragma unroll
    for (int j=0;j<4;j++)
        t[threadIdx.y+j*8][threadIdx.x] = in[(long long)(r0+threadIdx.y+j*8)*C + c0+threadIdx.x];
    __syncthreads();
    #pragma unroll
    for (int j=0;j<4;j++)
        out[(long long)(c0+threadIdx.y+j*8)*R + r0+threadIdx.x] = t[threadIdx.x][threadIdx.y+j*8];
}

// ---------------- mask dtype detection (0=int32,1=uint8,2=float32) ----------
__global__ void detect_mask_kernel(const uint32_t* __restrict__ m, int nw, int* __restrict__ f)
{
    __shared__ int wg, bb;
    if (threadIdx.x==0){ wg=0; bb=0; }
    __syncthreads();
    int lw=0, lb=0;
    for (int i=threadIdx.x;i<nw;i+=blockDim.x){
        uint32_t w = m[i];
        if (w>1u) lw=1;
        #pragma unroll
        for (int b=0;b<4;b++) if (((w>>(8*b))&0xFFu)>1u) lb=1;
    }
    if (lw) atomicOr(&wg,1);
    if (lb) atomicOr(&bb,1);
    __syncthreads();
    if (threadIdx.x==0) *f = (!wg)?0:((!bb)?1:2);
}

// ---------------- softmax / LN / add ----------------
__device__ __forceinline__ float blk_red(float v, bool mx){
    __shared__ float sh[256];
    int t = threadIdx.x; sh[t]=v; __syncthreads();
    #pragma unroll
    for (int s=128;s>0;s>>=1){ if (t<s) sh[t]= mx?fmaxf(sh[t],sh[t+s]):(sh[t]+sh[t+s]); __syncthreads(); }
    float r = sh[0]; __syncthreads(); return r;
}

template<int NIT>
__global__ __launch_bounds__(256)
void softmax_mask_kernel(float* __restrict__ S, const void* __restrict__ mask,
                         const int* __restrict__ mt_p, int Nk)
{
    const long long row = blockIdx.x;
    float* s = S + row*(long long)Nk;
    const long long mb = row*(long long)Nk;
    const int t = threadIdx.x, mt = *mt_p;
    float e[NIT]; float mx = -INFINITY;
    #pragma unroll
    for (int i=0;i<NIT;i++){
        int idx = t + i*256;
        float v = s[idx]; bool msk;
        if (mt==0)      msk = ((const int*)mask)[mb+idx]!=0;
        else if (mt==1) msk = ((const uint8_t*)mask)[mb+idx]!=0;
        else            msk = ((const float*)mask)[mb+idx]!=0.f;
        e[i] = msk ? -INFINITY : v;
        mx = fmaxf(mx, e[i]);
    }
    mx = blk_red(mx, true);
    float sum = 0.f;
    #pragma unroll
    for (int i=0;i<NIT;i++){ float ev = (e[i]==-INFINITY)?0.f:__expf(e[i]-mx); e[i]=ev; sum+=ev; }
    sum = blk_red(sum, false);
    float inv = (sum>0.f)?(1.f/sum):0.f;
    #pragma unroll
    for (int i=0;i<NIT;i++) s[t+i*256] = e[i]*inv;
}

__global__ __launch_bounds__(256)
void ln_res_kernel(const float* __restrict__ x, const float* __restrict__ res,
                   const float* __restrict__ gm, const float* __restrict__ bt,
                   float* __restrict__ out)
{
    const long long row = blockIdx.x;
    const int t = threadIdx.x;
    float v = x[row*HDIM+t];
    float mu = blk_red(v,false)*(1.f/HDIM);
    float d = v-mu;
    float var = blk_red(d*d,false)*(1.f/HDIM);
    out[row*HDIM+t] = d*rsqrtf(var+1e-5f)*gm[t]+bt[t] + res[row*HDIM+t];
}

__global__ void add_kernel(const float* __restrict__ a, const float* __restrict__ b,
                           float* __restrict__ o, long long n)
{
    long long i = (long long)blockIdx.x*blockDim.x + threadIdx.x;
    if (i<n) o[i] = a[i]+b[i];
}

// ---------------- host orchestration ----------------
static void gemm(const float* A, const float* B, const float* bias, float* C,
                 int M, int N, int K, long long sA, long long sB, long long sC,
                 float alpha, int nz)
{
    dim3 g(N/128, M/128, nz);
    if (bias) gemm_mma<true ><<<g, 512, GSMEM>>>(A,B,bias,C,N,K,sA,sB,sC,alpha);
    else      gemm_mma<false><<<g, 512, GSMEM>>>(A,B,nullptr,C,N,K,sA,sB,sC,alpha);
}

static void proj3(const float* x, int M, const float* wT, const float* b,
                  float* outp, float* t0, float* t1)
{
    gemm(x,  wT+0*65536, b+0*256, t0,   M,256,256, 0,0,0, 1.f, 1);
    gemm(t0, wT+1*65536, b+1*256, t1,   M,256,256, 0,0,0, 1.f, 1);
    gemm(t1, wT+2*65536, b+2*256, outp, M,256,256, 0,0,0, 1.f, 1);
}

static void run_layer(const float* x1, const float* x2, const void* mask,
                      const int* mt, int Nk,
                      const float* wqT, const float* bq_l,
                      const float* wkT, const float* bk_l,
                      const float* wvT, const float* bv_l,
                      const float* gm, const float* bt, float* xout,
                      float* t0, float* t1, float* q, float* k, float* v,
                      float* vt, float* s, float* at)
{
    const int Bb=16, Nq=1024;
    proj3(x1, Bb*Nq, wqT, bq_l, q, t0, t1);
    proj3(x2, Bb*Nk, wkT, bk_l, k, t0, t1);
    proj3(x2, Bb*Nk, wvT, bv_l, v, t0, t1);
    {   // V^T per batch
        dim3 g(HDIM/32, Nk/32, Bb);
        transpose_k<<<g, dim3(32,8)>>>(v, vt, Nk, HDIM, (long long)Nk*HDIM, (long long)Nk*HDIM);
    }
    // S = Q K^T / 16
    gemm(q, k, nullptr, s, Nq, Nk, HDIM,
         (long long)Nq*HDIM, (long long)Nk*HDIM, (long long)Nq*Nk, 0.0625f, Bb);
    if (Nk==1024) softmax_mask_kernel<4><<<Bb*Nq,256>>>(s, mask, mt, Nk);
    else          softmax_mask_kernel<8><<<Bb*Nq,256>>>(s, mask, mt, Nk);
    // X = S @ V  (NT against V^T)
    gemm(s, vt, nullptr, at, Nq, HDIM, Nk,
         (long long)Nq*Nk, (long long)Nk*HDIM, (long long)Nq*HDIM, 1.f, Bb);
    ln_res_kernel<<<Bb*Nq,256>>>(at, x1, gm, bt, xout);
}

extern "C" void kernel_launch(void* const* d_in, const int* in_sizes, int n_in,
                              void* d_out, int out_size)
{
    const float* future  = (const float*)d_in[0];
    const float* history = (const float*)d_in[1];
    const float* graph   = (const float*)d_in[2];
    const void*  mask_hf = d_in[3];
    const void*  mask_fg = d_in[4];
    const float* Wq = (const float*)d_in[5];
    const float* bq = (const float*)d_in[6];
    const float* Wk = (const float*)d_in[7];
    const float* bk = (const float*)d_in[8];
    const float* Wv = (const float*)d_in[9];
    const float* bv = (const float*)d_in[10];
    const float* gm = (const float*)d_in[11];
    const float* bt = (const float*)d_in[12];
    float* out = (float*)d_out;

    // dynamic smem opt-in (capture-safe: no stream work). Idempotent.
    cudaFuncSetAttribute(gemm_mma<true >, cudaFuncAttributeMaxDynamicSharedMemorySize, GSMEM);
    cudaFuncSetAttribute(gemm_mma<false>, cudaFuncAttributeMaxDynamicSharedMemorySize, GSMEM);

    float *t0,*t1,*q,*k,*v,*vt,*s,*at,*xA,*xB,*wqT,*wkT,*wvT;
    int *mhf,*mfg;
    cudaGetSymbolAddress((void**)&t0,g_t0);   cudaGetSymbolAddress((void**)&t1,g_t1);
    cudaGetSymbolAddress((void**)&q,g_q);     cudaGetSymbolAddress((void**)&k,g_k);
    cudaGetSymbolAddress((void**)&v,g_v);     cudaGetSymbolAddress((void**)&vt,g_vt);
    cudaGetSymbolAddress((void**)&s,g_s);     cudaGetSymbolAddress((void**)&at,g_at);
    cudaGetSymbolAddress((void**)&xA,g_xA);   cudaGetSymbolAddress((void**)&xB,g_xB);
    cudaGetSymbolAddress((void**)&wqT,g_wqT); cudaGetSymbolAddress((void**)&wkT,g_wkT);
    cudaGetSymbolAddress((void**)&wvT,g_wvT);
    cudaGetSymbolAddress((void**)&mhf,g_mt_hf); cudaGetSymbolAddress((void**)&mfg,g_mt_fg);

    {
        int nh = in_sizes[3]/4; if (nh>65536) nh=65536;
        int ng = in_sizes[4]/4; if (ng>65536) ng=65536;
        detect_mask_kernel<<<1,256>>>((const uint32_t*)mask_hf, nh, mhf);
        detect_mask_kernel<<<1,256>>>((const uint32_t*)mask_fg, ng, mfg);
    }
    {   // transpose all 12 weight matrices per tensor (layer-major batch)
        dim3 g(8,8,12), b(32,8);
        transpose_k<<<g,b>>>(Wq, wqT, 256,256, 65536,65536);
        transpose_k<<<g,b>>>(Wk, wkT, 256,256, 65536,65536);
        transpose_k<<<g,b>>>(Wv, wvT, 256,256, 65536,65536);
    }

    const long long WL = 3LL*65536, BL = 3LL*256;
    run_layer(future, history, mask_hf, mhf, 1024,
              wqT+0*WL, bq+0*BL, wkT+0*WL, bk+0*BL, wvT+0*WL, bv+0*BL,
              gm+0*256, bt+0*256, xA, t0,t1,q,k,v,vt,s,at);
    run_layer(xA, history, mask_hf, mhf, 1024,
              wqT+1*WL, bq+1*BL, wkT+1*WL, bk+1*BL, wvT+1*WL, bv+1*BL,
              gm+1*256, bt+1*256, xB, t0,t1,q,k,v,vt,s,at);
    run_layer(xB, graph, mask_fg, mfg, 2048,
              wqT+2*WL, bq+2*BL, wkT+2*WL, bk+2*BL, wvT+2*WL, bv+2*BL,
              gm+2*256, bt+2*256, xA, t0,t1,q,k,v,vt,s,at);
    run_layer(xA, graph, mask_fg, mfg, 2048,
              wqT+3*WL, bq+3*BL, wkT+3*WL, bk+3*BL, wvT+3*WL, bv+3*BL,
              gm+3*256, bt+3*256, xB, t0,t1,q,k,v,vt,s,at);

    long long n = (long long)out_size;
    add_kernel<<<(unsigned)((n+255)/256),256>>>(future, xB, out, n);
}

// round 8
// speedup vs baseline: 2.4728x; 1.0646x over previous
// bf16-split mma.sync + fused projection chains. CrossEncoder4FutureTrajectory.
#include <cuda_runtime.h>
#include <cuda_bf16.h>
#include <cstdint>
#include <math.h>

#define HDIM 256
typedef __nv_bfloat16 bf16;

// ---------------- scratch (device globals) ----------------
__device__ float g_q [16*1024*256];
__device__ float g_k [16*2048*256];
__device__ float g_v [16*2048*256];
__device__ float g_vt[16*2048*256];
__device__ float g_s [16LL*1024*2048];
__device__ float g_at[16*1024*256];
__device__ float g_xA[16*1024*256];
__device__ float g_xB[16*1024*256];
__device__ float g_wqT[12*65536];
__device__ float g_wkT[12*65536];
__device__ float g_wvT[12*65536];
__device__ int g_mt_hf, g_mt_fg;

// ---------------- helpers ----------------
__device__ __forceinline__ uint32_t smem_u32(const void* p){
    uint32_t a; asm("{ .reg .u64 t; cvta.to.shared.u64 t, %1; cvt.u32.u64 %0, t; }":"=r"(a):"l"(p)); return a;
}
__device__ __forceinline__ void ldsm4(uint32_t addr, uint32_t* r){
    asm volatile("ldmatrix.sync.aligned.m8n8.x4.shared.b16 {%0,%1,%2,%3}, [%4];"
        : "=r"(r[0]),"=r"(r[1]),"=r"(r[2]),"=r"(r[3]) : "r"(addr));
}
__device__ __forceinline__ void mma16816(float* c, const uint32_t* a, const uint32_t* b){
    asm volatile("mma.sync.aligned.m16n8k16.row.col.f32.bf16.bf16.f32 "
        "{%0,%1,%2,%3},{%4,%5,%6,%7},{%8,%9},{%0,%1,%2,%3};"
        : "+f"(c[0]),"+f"(c[1]),"+f"(c[2]),"+f"(c[3])
        : "r"(a[0]),"r"(a[1]),"r"(a[2]),"r"(a[3]),"r"(b[0]),"r"(b[1]));
}
__device__ __forceinline__ void split4(float4 v, uint2& h, uint2& l){
    bf16 hb[4], lb[4];
    float xs[4] = {v.x, v.y, v.z, v.w};
    #pragma unroll
    for (int i=0;i<4;i++){ hb[i]=__float2bfloat16(xs[i]); lb[i]=__float2bfloat16(xs[i]-__bfloat162float(hb[i])); }
    h = *(uint2*)hb; l = *(uint2*)lb;
}

// ============================================================================
// Fused 3-stage projection: Out = L2(L1(L0(X))), each Li: Y = X @ Wi^T + bi.
// X [M,256] fp32; WT [3][256,256] fp32 (pre-transposed, NT); Out [M,256] fp32.
// CTA owns 128 rows through all 3 stages. A resident in smem (bf16 hi/lo,
// row stride 264 hw = 528B, ldmatrix conflict-free). W streamed per K-chunk 64
// into [256][72] hi/lo. 512 thr, 4x4 warps, warp tile 32x64, 64 acc/thread.
// ============================================================================
#define ASST 264
#define BSST 72
#define PSMEM ((2*128*ASST + 2*256*BSST)*2)   // 208896 B

__global__ __launch_bounds__(512, 1)
void proj_fused(const float* __restrict__ X, const float* __restrict__ WT,
                const float* __restrict__ bias, float* __restrict__ Out)
{
    extern __shared__ bf16 sm[];
    bf16* sAh = sm;
    bf16* sAl = sm + 128*ASST;
    bf16* sBh = sm + 2*128*ASST;
    bf16* sBl = sm + 2*128*ASST + 256*BSST;

    const int tid = threadIdx.x, warp = tid>>5, lane = tid&31;
    const int wm = warp>>2, wn = warp&3;
    const long long m0 = (long long)blockIdx.x * 128;

    const uint32_t bAh = smem_u32(sAh), bAl = smem_u32(sAl);
    const uint32_t bBh = smem_u32(sBh), bBl = smem_u32(sBl);

    // load X rows into sA (split). 128x64 float4 -> 16/thread.
    #pragma unroll
    for (int i=0;i<16;i++){
        int id = tid + (i<<9);
        int r = id>>6, c4 = (id&63)<<2;
        uint2 h, l;
        split4(*(const float4*)(X + (m0+r)*256 + c4), h, l);
        *(uint2*)(sAh + r*ASST + c4) = h;
        *(uint2*)(sAl + r*ASST + c4) = l;
    }

    float acc[2][8][4];

    #pragma unroll 1
    for (int s=0; s<3; s++){
        const float* W  = WT + s*65536;
        const float* bp = bias + s*256;
        #pragma unroll
        for (int mi=0;mi<2;mi++)
            #pragma unroll
            for (int ni=0;ni<8;ni++)
                #pragma unroll
                for (int t=0;t<4;t++) acc[mi][ni][t] = 0.f;

        #pragma unroll 1
        for (int kc=0; kc<4; kc++){
            const int k0 = kc<<6;
            // fill W chunk: 256 rows x 16 float4 -> 8/thread
            #pragma unroll
            for (int i=0;i<8;i++){
                int id = tid + (i<<9);
                int r = id>>4, c4 = (id&15)<<2;
                uint2 h, l;
                split4(*(const float4*)(W + r*256 + k0 + c4), h, l);
                *(uint2*)(sBh + r*BSST + c4) = h;
                *(uint2*)(sBl + r*BSST + c4) = l;
            }
            __syncthreads();

            #pragma unroll
            for (int k16=0; k16<4; k16++){
                const uint32_t acol = (k0 + k16*16)*2 + ((lane>>4)<<4);
                const uint32_t arow = (wm*32 + (lane&15)) * (ASST*2);
                uint32_t Ah[2][4], Al[2][4];
                #pragma unroll
                for (int mi=0;mi<2;mi++){
                    ldsm4(bAh + arow + mi*16*(ASST*2) + acol, Ah[mi]);
                    ldsm4(bAl + arow + mi*16*(ASST*2) + acol, Al[mi]);
                }
                const uint32_t bcol = k16*32 + (((lane>>3)&1)<<4);
                #pragma unroll
                for (int bi=0;bi<4;bi++){
                    const uint32_t brow = (wn*64 + bi*16 + ((lane>>4)<<3) + (lane&7)) * (BSST*2);
                    uint32_t Bh[4], Bl[4];
                    ldsm4(bBh + brow + bcol, Bh);
                    ldsm4(bBl + brow + bcol, Bl);
                    #pragma unroll
                    for (int mi=0;mi<2;mi++)
                        #pragma unroll
                        for (int nh=0;nh<2;nh++){
                            int ni = bi*2+nh;
                            mma16816(acc[mi][ni], Ah[mi], &Bh[nh*2]);
                            mma16816(acc[mi][ni], Ah[mi], &Bl[nh*2]);
                            mma16816(acc[mi][ni], Al[mi], &Bh[nh*2]);
                        }
                }
            }
            __syncthreads();
        }

        // epilogue: bias; stages 0,1 -> back into sA (split); stage 2 -> gmem.
        const int rbase = wm*32 + (lane>>2);
        const int cbase = wn*64 + (lane&3)*2;
        if (s < 2){
            #pragma unroll
            for (int mi=0;mi<2;mi++)
                #pragma unroll
                for (int ni=0;ni<8;ni++)
                    #pragma unroll
                    for (int half=0; half<2; half++){
                        int r = rbase + mi*16 + half*8;
                        int c = cbase + ni*8;
                        float v0 = acc[mi][ni][half*2+0] + __ldg(bp+c);
                        float v1 = acc[mi][ni][half*2+1] + __ldg(bp+c+1);
                        bf16 h0 = __float2bfloat16(v0);
                        bf16 h1 = __float2bfloat16(v1);
                        sAh[r*ASST+c]   = h0;
                        sAh[r*ASST+c+1] = h1;
                        sAl[r*ASST+c]   = __float2bfloat16(v0 - __bfloat162float(h0));
                        sAl[r*ASST+c+1] = __float2bfloat16(v1 - __bfloat162float(h1));
                    }
            __syncthreads();
        } else {
            #pragma unroll
            for (int mi=0;mi<2;mi++)
                #pragma unroll
                for (int ni=0;ni<8;ni++)
                    #pragma unroll
                    for (int half=0; half<2; half++){
                        int r = rbase + mi*16 + half*8;
                        int c = cbase + ni*8;
                        float2 v;
                        v.x = acc[mi][ni][half*2+0] + __ldg(bp+c);
                        v.y = acc[mi][ni][half*2+1] + __ldg(bp+c+1);
                        *(float2*)(Out + (m0+r)*256 + c) = v;
                    }
        }
    }
}

// ============================================================================
// NT GEMM via mma.sync (unchanged from R7): C = alpha*(A @ B^T) (+bias).
// CTA 128x128, K-chunk 64, 512 thr, register prefetch double-buffer.
// ============================================================================
#define SST 72
#define GSMEM (4*128*SST*2)

template<bool BIAS>
__global__ __launch_bounds__(512)
void gemm_mma(const float* __restrict__ A, const float* __restrict__ B,
              const float* __restrict__ bias, float* __restrict__ C,
              int N, int K, long long szA, long long szB, long long szC, float alpha)
{
    extern __shared__ bf16 smem[];
    bf16* sAh = smem;
    bf16* sAl = smem + 128*SST;
    bf16* sBh = smem + 2*128*SST;
    bf16* sBl = smem + 3*128*SST;

    const int tid = threadIdx.x, warp = tid>>5, lane = tid&31;
    const int wm = warp>>2, wn = warp&3;
    const int m0 = blockIdx.y*128, n0 = blockIdx.x*128, z = blockIdx.z;
    A += (long long)z*szA; B += (long long)z*szB;

    const uint32_t bAh = smem_u32(sAh), bAl = smem_u32(sAl);
    const uint32_t bBh = smem_u32(sBh), bBl = smem_u32(sBl);

    float acc[2][4][4];
    #pragma unroll
    for (int i=0;i<2;i++)
        #pragma unroll
        for (int j=0;j<4;j++)
            #pragma unroll
            for (int t=0;t<4;t++) acc[i][j][t] = 0.f;

    int fr[4], fc[4];
    #pragma unroll
    for (int i=0;i<4;i++){ int id = tid + (i<<9); fr[i]=id>>4; fc[i]=(id&15)<<2; }

    float4 pA[4], pB[4];
    #pragma unroll
    for (int i=0;i<4;i++){
        pA[i] = *(const float4*)(A + (long long)(m0+fr[i])*K + fc[i]);
        pB[i] = *(const float4*)(B + (long long)(n0+fr[i])*K + fc[i]);
    }

    const int nch = K >> 6;
    for (int kc=0; kc<nch; kc++){
        #pragma unroll
        for (int i=0;i<4;i++){
            uint2 h, l;
            split4(pA[i], h, l);
            *(uint2*)(sAh + fr[i]*SST + fc[i]) = h;
            *(uint2*)(sAl + fr[i]*SST + fc[i]) = l;
            split4(pB[i], h, l);
            *(uint2*)(sBh + fr[i]*SST + fc[i]) = h;
            *(uint2*)(sBl + fr[i]*SST + fc[i]) = l;
        }
        __syncthreads();

        if (kc+1 < nch){
            const int k0 = (kc+1)<<6;
            #pragma unroll
            for (int i=0;i<4;i++){
                pA[i] = *(const float4*)(A + (long long)(m0+fr[i])*K + k0 + fc[i]);
                pB[i] = *(const float4*)(B + (long long)(n0+fr[i])*K + k0 + fc[i]);
            }
        }

        #pragma unroll
        for (int k16=0; k16<4; k16++){
            const uint32_t akoff = k16*32 + ((lane>>4)<<4);
            const uint32_t bkoff = k16*32 + (((lane>>3)&1)<<4);
            const uint32_t arow  = (wm*32 + (lane&15)) * (SST*2);
            const uint32_t brow  = (wn*32 + ((lane>>4)<<3) + (lane&7)) * (SST*2);

            uint32_t Ah[2][4], Al[2][4], Bh[2][4], Bl[2][4];
            #pragma unroll
            for (int mi=0;mi<2;mi++){
                ldsm4(bAh + arow + mi*16*(SST*2) + akoff, Ah[mi]);
                ldsm4(bAl + arow + mi*16*(SST*2) + akoff, Al[mi]);
            }
            #pragma unroll
            for (int bi=0;bi<2;bi++){
                ldsm4(bBh + brow + bi*16*(SST*2) + bkoff, Bh[bi]);
                ldsm4(bBl + brow + bi*16*(SST*2) + bkoff, Bl[bi]);
            }
            #pragma unroll
            for (int mi=0;mi<2;mi++)
                #pragma unroll
                for (int ni=0;ni<4;ni++){
                    mma16816(acc[mi][ni], Ah[mi], &Bh[ni>>1][(ni&1)*2]);
                    mma16816(acc[mi][ni], Ah[mi], &Bl[ni>>1][(ni&1)*2]);
                    mma16816(acc[mi][ni], Al[mi], &Bh[ni>>1][(ni&1)*2]);
                }
        }
        __syncthreads();
    }

    C += (long long)z*szC;
    const int mrow = m0 + wm*32 + (lane>>2);
    const int ncol = n0 + wn*32 + (lane&3)*2;
    #pragma unroll
    for (int mi=0;mi<2;mi++)
        #pragma unroll
        for (int ni=0;ni<4;ni++)
            #pragma unroll
            for (int half=0; half<2; half++){
                int r = mrow + mi*16 + half*8;
                int c = ncol + ni*8;
                float2 v;
                v.x = acc[mi][ni][half*2+0]*alpha;
                v.y = acc[mi][ni][half*2+1]*alpha;
                if (BIAS){ v.x += __ldg(bias+c); v.y += __ldg(bias+c+1); }
                *(float2*)(C + (long long)r*N + c) = v;
            }
}

// ---------------- transpose: out[z][c][r] = in[z][r][c] ----------------
__global__ void transpose_k(const float* __restrict__ in, float* __restrict__ out,
                            int R, int C, long long sIn, long long sOut)
{
    __shared__ float t[32][33];
    const int z = blockIdx.z;
    in += (long long)z*sIn; out += (long long)z*sOut;
    int r0 = blockIdx.y*32, c0 = blockIdx.x*32;
    #pragma unroll
    for (int j=0;j<4;j++)
        t[threadIdx.y+j*8][threadIdx.x] = in[(long long)(r0+threadIdx.y+j*8)*C + c0+threadIdx.x];
    __syncthreads();
    #pragma unroll
    for (int j=0;j<4;j++)
        out[(long long)(c0+threadIdx.y+j*8)*R + r0+threadIdx.x] = t[threadIdx.x][threadIdx.y+j*8];
}

// ---------------- mask dtype detection (0=int32,1=uint8,2=float32) ----------
__global__ void detect_mask_kernel(const uint32_t* __restrict__ m, int nw, int* __restrict__ f)
{
    __shared__ int wg, bb;
    if (threadIdx.x==0){ wg=0; bb=0; }
    __syncthreads();
    int lw=0, lb=0;
    for (int i=threadIdx.x;i<nw;i+=blockDim.x){
        uint32_t w = m[i];
        if (w>1u) lw=1;
        #pragma unroll
        for (int b=0;b<4;b++) if (((w>>(8*b))&0xFFu)>1u) lb=1;
    }
    if (lw) atomicOr(&wg,1);
    if (lb) atomicOr(&bb,1);
    __syncthreads();
    if (threadIdx.x==0) *f = (!wg)?0:((!bb)?1:2);
}

// ---------------- softmax / LN / add ----------------
__device__ __forceinline__ float blk_red(float v, bool mx){
    __shared__ float sh[256];
    int t = threadIdx.x; sh[t]=v; __syncthreads();
    #pragma unroll
    for (int s=128;s>0;s>>=1){ if (t<s) sh[t]= mx?fmaxf(sh[t],sh[t+s]):(sh[t]+sh[t+s]); __syncthreads(); }
    float r = sh[0]; __syncthreads(); return r;
}

template<int NIT>
__global__ __launch_bounds__(256)
void softmax_mask_kernel(float* __restrict__ S, const void* __restrict__ mask,
                         const int* __restrict__ mt_p, int Nk)
{
    const long long row = blockIdx.x;
    float* s = S + row*(long long)Nk;
    const long long mb = row*(long long)Nk;
    const int t = threadIdx.x, mt = *mt_p;
    float e[NIT]; float mx = -INFINITY;
    #pragma unroll
    for (int i=0;i<NIT;i++){
        int idx = t + i*256;
        float v = s[idx]; bool msk;
        if (mt==0)      msk = ((const int*)mask)[mb+idx]!=0;
        else if (mt==1) msk = ((const uint8_t*)mask)[mb+idx]!=0;
        else            msk = ((const float*)mask)[mb+idx]!=0.f;
        e[i] = msk ? -INFINITY : v;
        mx = fmaxf(mx, e[i]);
    }
    mx = blk_red(mx, true);
    float sum = 0.f;
    #pragma unroll
    for (int i=0;i<NIT;i++){ float ev = (e[i]==-INFINITY)?0.f:__expf(e[i]-mx); e[i]=ev; sum+=ev; }
    sum = blk_red(sum, false);
    float inv = (sum>0.f)?(1.f/sum):0.f;
    #pragma unroll
    for (int i=0;i<NIT;i++) s[t+i*256] = e[i]*inv;
}

__global__ __launch_bounds__(256)
void ln_res_kernel(const float* __restrict__ x, const float* __restrict__ res,
                   const float* __restrict__ gm, const float* __restrict__ bt,
                   float* __restrict__ out)
{
    const long long row = blockIdx.x;
    const int t = threadIdx.x;
    float v = x[row*HDIM+t];
    float mu = blk_red(v,false)*(1.f/HDIM);
    float d = v-mu;
    float var = blk_red(d*d,false)*(1.f/HDIM);
    out[row*HDIM+t] = d*rsqrtf(var+1e-5f)*gm[t]+bt[t] + res[row*HDIM+t];
}

__global__ void add_kernel(const float* __restrict__ a, const float* __restrict__ b,
                           float* __restrict__ o, long long n)
{
    long long i = (long long)blockIdx.x*blockDim.x + threadIdx.x;
    if (i<n) o[i] = a[i]+b[i];
}

// ---------------- host orchestration ----------------
static void gemm(const float* A, const float* B, const float* bias, float* C,
                 int M, int N, int K, long long sA, long long sB, long long sC,
                 float alpha, int nz)
{
    dim3 g(N/128, M/128, nz);
    if (bias) gemm_mma<true ><<<g, 512, GSMEM>>>(A,B,bias,C,N,K,sA,sB,sC,alpha);
    else      gemm_mma<false><<<g, 512, GSMEM>>>(A,B,nullptr,C,N,K,sA,sB,sC,alpha);
}

static void run_layer(const float* x1, const float* x2, const void* mask,
                      const int* mt, int Nk,
                      const float* wqT, const float* bq_l,
                      const float* wkT, const float* bk_l,
                      const float* wvT, const float* bv_l,
                      const float* gm, const float* bt, float* xout,
                      float* q, float* k, float* v,
                      float* vt, float* s, float* at)
{
    const int Bb=16, Nq=1024;
    proj_fused<<<Bb*Nq/128, 512, PSMEM>>>(x1, wqT, bq_l, q);
    proj_fused<<<Bb*Nk/128, 512, PSMEM>>>(x2, wkT, bk_l, k);
    proj_fused<<<Bb*Nk/128, 512, PSMEM>>>(x2, wvT, bv_l, v);
    {   // V^T per batch
        dim3 g(HDIM/32, Nk/32, Bb);
        transpose_k<<<g, dim3(32,8)>>>(v, vt, Nk, HDIM, (long long)Nk*HDIM, (long long)Nk*HDIM);
    }
    // S = Q K^T / 16
    gemm(q, k, nullptr, s, Nq, Nk, HDIM,
         (long long)Nq*HDIM, (long long)Nk*HDIM, (long long)Nq*Nk, 0.0625f, Bb);
    if (Nk==1024) softmax_mask_kernel<4><<<Bb*Nq,256>>>(s, mask, mt, Nk);
    else          softmax_mask_kernel<8><<<Bb*Nq,256>>>(s, mask, mt, Nk);
    // X = S @ V  (NT against V^T)
    gemm(s, vt, nullptr, at, Nq, HDIM, Nk,
         (long long)Nq*Nk, (long long)Nk*HDIM, (long long)Nq*HDIM, 1.f, Bb);
    ln_res_kernel<<<Bb*Nq,256>>>(at, x1, gm, bt, xout);
}

extern "C" void kernel_launch(void* const* d_in, const int* in_sizes, int n_in,
                              void* d_out, int out_size)
{
    const float* future  = (const float*)d_in[0];
    const float* history = (const float*)d_in[1];
    const float* graph   = (const float*)d_in[2];
    const void*  mask_hf = d_in[3];
    const void*  mask_fg = d_in[4];
    const float* Wq = (const float*)d_in[5];
    const float* bq = (const float*)d_in[6];
    const float* Wk = (const float*)d_in[7];
    const float* bk = (const float*)d_in[8];
    const float* Wv = (const float*)d_in[9];
    const float* bv = (const float*)d_in[10];
    const float* gm = (const float*)d_in[11];
    const float* bt = (const float*)d_in[12];
    float* out = (float*)d_out;

    // dynamic smem opt-in (capture-safe host-side attribute; idempotent)
    cudaFuncSetAttribute(gemm_mma<true >, cudaFuncAttributeMaxDynamicSharedMemorySize, GSMEM);
    cudaFuncSetAttribute(gemm_mma<false>, cudaFuncAttributeMaxDynamicSharedMemorySize, GSMEM);
    cudaFuncSetAttribute(proj_fused,      cudaFuncAttributeMaxDynamicSharedMemorySize, PSMEM);

    float *q,*k,*v,*vt,*s,*at,*xA,*xB,*wqT,*wkT,*wvT;
    int *mhf,*mfg;
    cudaGetSymbolAddress((void**)&q,g_q);     cudaGetSymbolAddress((void**)&k,g_k);
    cudaGetSymbolAddress((void**)&v,g_v);     cudaGetSymbolAddress((void**)&vt,g_vt);
    cudaGetSymbolAddress((void**)&s,g_s);     cudaGetSymbolAddress((void**)&at,g_at);
    cudaGetSymbolAddress((void**)&xA,g_xA);   cudaGetSymbolAddress((void**)&xB,g_xB);
    cudaGetSymbolAddress((void**)&wqT,g_wqT); cudaGetSymbolAddress((void**)&wkT,g_wkT);
    cudaGetSymbolAddress((void**)&wvT,g_wvT);
    cudaGetSymbolAddress((void**)&mhf,g_mt_hf); cudaGetSymbolAddress((void**)&mfg,g_mt_fg);

    {
        int nh = in_sizes[3]/4; if (nh>65536) nh=65536;
        int ng = in_sizes[4]/4; if (ng>65536) ng=65536;
        detect_mask_kernel<<<1,256>>>((const uint32_t*)mask_hf, nh, mhf);
        detect_mask_kernel<<<1,256>>>((const uint32_t*)mask_fg, ng, mfg);
    }
    {   // transpose all 12 weight matrices per tensor (layer-major batch)
        dim3 g(8,8,12), b(32,8);
        transpose_k<<<g,b>>>(Wq, wqT, 256,256, 65536,65536);
        transpose_k<<<g,b>>>(Wk, wkT, 256,256, 65536,65536);
        transpose_k<<<g,b>>>(Wv, wvT, 256,256, 65536,65536);
    }

    const long long WL = 3LL*65536, BL = 3LL*256;
    run_layer(future, history, mask_hf, mhf, 1024,
              wqT+0*WL, bq+0*BL, wkT+0*WL, bk+0*BL, wvT+0*WL, bv+0*BL,
              gm+0*256, bt+0*256, xA, q,k,v,vt,s,at);
    run_layer(xA, history, mask_hf, mhf, 1024,
              wqT+1*WL, bq+1*BL, wkT+1*WL, bk+1*BL, wvT+1*WL, bv+1*BL,
              gm+1*256, bt+1*256, xB, q,k,v,vt,s,at);
    run_layer(xB, graph, mask_fg, mfg, 2048,
              wqT+2*WL, bq+2*BL, wkT+2*WL, bk+2*BL, wvT+2*WL, bv+2*BL,
              gm+2*256, bt+2*256, xA, q,k,v,vt,s,at);
    run_layer(xA, graph, mask_fg, mfg, 2048,
              wqT+3*WL, bq+3*BL, wkT+3*WL, bk+3*BL, wvT+3*WL, bv+3*BL,
              gm+3*256, bt+3*256, xB, q,k,v,vt,s,at);

    long long n = (long long)out_size;
    add_kernel<<<(unsigned)((n+255)/256),256>>>(future, xB, out, n);
}

// round 9
// speedup vs baseline: 2.4868x; 1.0056x over previous
// bf16-split mma.sync + fused proj chains + fused softmax-stats attention.
#include <cuda_runtime.h>
#include <cuda_bf16.h>
#include <cstdint>
#include <math.h>

#define HDIM 256
typedef __nv_bfloat16 bf16;

// ---------------- scratch (device globals) ----------------
__device__ float g_q [16*1024*256];
__device__ float g_k [16*2048*256];
__device__ float g_v [16*2048*256];
__device__ float g_vt[16*2048*256];
__device__ float g_s [16LL*1024*2048];
__device__ float g_at[16*1024*256];
__device__ float g_xA[16*1024*256];
__device__ float g_xB[16*1024*256];
__device__ float g_wqT[12*65536];
__device__ float g_wkT[12*65536];
__device__ float g_wvT[12*65536];
__device__ float2 g_stats[16*1024*16];   // per-(row, n-tile) partial (max, sum)
__device__ float2 g_rs[16*1024];         // per-row (max, 1/l)
__device__ int g_mt_hf, g_mt_fg;

// ---------------- helpers ----------------
__device__ __forceinline__ uint32_t smem_u32(const void* p){
    uint32_t a; asm("{ .reg .u64 t; cvta.to.shared.u64 t, %1; cvt.u32.u64 %0, t; }":"=r"(a):"l"(p)); return a;
}
__device__ __forceinline__ void ldsm4(uint32_t addr, uint32_t* r){
    asm volatile("ldmatrix.sync.aligned.m8n8.x4.shared.b16 {%0,%1,%2,%3}, [%4];"
        : "=r"(r[0]),"=r"(r[1]),"=r"(r[2]),"=r"(r[3]) : "r"(addr));
}
__device__ __forceinline__ void mma16816(float* c, const uint32_t* a, const uint32_t* b){
    asm volatile("mma.sync.aligned.m16n8k16.row.col.f32.bf16.bf16.f32 "
        "{%0,%1,%2,%3},{%4,%5,%6,%7},{%8,%9},{%0,%1,%2,%3};"
        : "+f"(c[0]),"+f"(c[1]),"+f"(c[2]),"+f"(c[3])
        : "r"(a[0]),"r"(a[1]),"r"(a[2]),"r"(a[3]),"r"(b[0]),"r"(b[1]));
}
__device__ __forceinline__ void split4(float4 v, uint2& h, uint2& l){
    bf16 hb[4], lb[4];
    float xs[4] = {v.x, v.y, v.z, v.w};
    #pragma unroll
    for (int i=0;i<4;i++){ hb[i]=__float2bfloat16(xs[i]); lb[i]=__float2bfloat16(xs[i]-__bfloat162float(hb[i])); }
    h = *(uint2*)hb; l = *(uint2*)lb;
}
__device__ __forceinline__ bool mchk(const void* m, int mt, long long idx){
    if (mt==0) return ((const int*)m)[idx]!=0;
    if (mt==1) return ((const uint8_t*)m)[idx]!=0;
    return ((const float*)m)[idx]!=0.f;
}

// ============================================================================
// Fused 3-stage projection (unchanged from R8).
// ============================================================================
#define ASST 264
#define BSST 72
#define PSMEM ((2*128*ASST + 2*256*BSST)*2)

__global__ __launch_bounds__(512, 1)
void proj_fused(const float* __restrict__ X, const float* __restrict__ WT,
                const float* __restrict__ bias, float* __restrict__ Out)
{
    extern __shared__ bf16 sm[];
    bf16* sAh = sm;
    bf16* sAl = sm + 128*ASST;
    bf16* sBh = sm + 2*128*ASST;
    bf16* sBl = sm + 2*128*ASST + 256*BSST;

    const int tid = threadIdx.x, warp = tid>>5, lane = tid&31;
    const int wm = warp>>2, wn = warp&3;
    const long long m0 = (long long)blockIdx.x * 128;

    const uint32_t bAh = smem_u32(sAh), bAl = smem_u32(sAl);
    const uint32_t bBh = smem_u32(sBh), bBl = smem_u32(sBl);

    #pragma unroll
    for (int i=0;i<16;i++){
        int id = tid + (i<<9);
        int r = id>>6, c4 = (id&63)<<2;
        uint2 h, l;
        split4(*(const float4*)(X + (m0+r)*256 + c4), h, l);
        *(uint2*)(sAh + r*ASST + c4) = h;
        *(uint2*)(sAl + r*ASST + c4) = l;
    }

    float acc[2][8][4];

    #pragma unroll 1
    for (int s=0; s<3; s++){
        const float* W  = WT + s*65536;
        const float* bp = bias + s*256;
        #pragma unroll
        for (int mi=0;mi<2;mi++)
            #pragma unroll
            for (int ni=0;ni<8;ni++)
                #pragma unroll
                for (int t=0;t<4;t++) acc[mi][ni][t] = 0.f;

        #pragma unroll 1
        for (int kc=0; kc<4; kc++){
            const int k0 = kc<<6;
            #pragma unroll
            for (int i=0;i<8;i++){
                int id = tid + (i<<9);
                int r = id>>4, c4 = (id&15)<<2;
                uint2 h, l;
                split4(*(const float4*)(W + r*256 + k0 + c4), h, l);
                *(uint2*)(sBh + r*BSST + c4) = h;
                *(uint2*)(sBl + r*BSST + c4) = l;
            }
            __syncthreads();

            #pragma unroll
            for (int k16=0; k16<4; k16++){
                const uint32_t acol = (k0 + k16*16)*2 + ((lane>>4)<<4);
                const uint32_t arow = (wm*32 + (lane&15)) * (ASST*2);
                uint32_t Ah[2][4], Al[2][4];
                #pragma unroll
                for (int mi=0;mi<2;mi++){
                    ldsm4(bAh + arow + mi*16*(ASST*2) + acol, Ah[mi]);
                    ldsm4(bAl + arow + mi*16*(ASST*2) + acol, Al[mi]);
                }
                const uint32_t bcol = k16*32 + (((lane>>3)&1)<<4);
                #pragma unroll
                for (int bi=0;bi<4;bi++){
                    const uint32_t brow = (wn*64 + bi*16 + ((lane>>4)<<3) + (lane&7)) * (BSST*2);
                    uint32_t Bh[4], Bl[4];
                    ldsm4(bBh + brow + bcol, Bh);
                    ldsm4(bBl + brow + bcol, Bl);
                    #pragma unroll
                    for (int mi=0;mi<2;mi++)
                        #pragma unroll
                        for (int nh=0;nh<2;nh++){
                            int ni = bi*2+nh;
                            mma16816(acc[mi][ni], Ah[mi], &Bh[nh*2]);
                            mma16816(acc[mi][ni], Ah[mi], &Bl[nh*2]);
                            mma16816(acc[mi][ni], Al[mi], &Bh[nh*2]);
                        }
                }
            }
            __syncthreads();
        }

        const int rbase = wm*32 + (lane>>2);
        const int cbase = wn*64 + (lane&3)*2;
        if (s < 2){
            #pragma unroll
            for (int mi=0;mi<2;mi++)
                #pragma unroll
                for (int ni=0;ni<8;ni++)
                    #pragma unroll
                    for (int half=0; half<2; half++){
                        int r = rbase + mi*16 + half*8;
                        int c = cbase + ni*8;
                        float v0 = acc[mi][ni][half*2+0] + __ldg(bp+c);
                        float v1 = acc[mi][ni][half*2+1] + __ldg(bp+c+1);
                        bf16 h0 = __float2bfloat16(v0);
                        bf16 h1 = __float2bfloat16(v1);
                        sAh[r*ASST+c]   = h0;
                        sAh[r*ASST+c+1] = h1;
                        sAl[r*ASST+c]   = __float2bfloat16(v0 - __bfloat162float(h0));
                        sAl[r*ASST+c+1] = __float2bfloat16(v1 - __bfloat162float(h1));
                    }
            __syncthreads();
        } else {
            #pragma unroll
            for (int mi=0;mi<2;mi++)
                #pragma unroll
                for (int ni=0;ni<8;ni++)
                    #pragma unroll
                    for (int half=0; half<2; half++){
                        int r = rbase + mi*16 + half*8;
                        int c = cbase + ni*8;
                        float2 v;
                        v.x = acc[mi][ni][half*2+0] + __ldg(bp+c);
                        v.y = acc[mi][ni][half*2+1] + __ldg(bp+c+1);
                        *(float2*)(Out + (m0+r)*256 + c) = v;
                    }
        }
    }
}

// ============================================================================
// Attention GEMMs. MODE 0 (QK): C = masked(alpha*A@B^T), epilogue emits
// per-(row,tile) softmax partials (max, sum) to stats. MODE 1 (SV): A values
// transformed a = exp(s - m)*invl on load (softmax applied in-GEMM).
// CTA 128x128, K-chunk 64, 512 thr, register prefetch (same core as R7/R8).
// ============================================================================
#define SST 72
#define GSMEM (4*128*SST*2)

template<int MODE>
__global__ __launch_bounds__(512)
void gemm_attn(const float* __restrict__ A, const float* __restrict__ B,
               float* __restrict__ C, int N, int K,
               long long szA, long long szB, long long szC, float alpha,
               const void* __restrict__ mask, const int* __restrict__ mtp,
               float2* __restrict__ stats, const float2* __restrict__ rs)
{
    extern __shared__ bf16 smem[];
    bf16* sAh = smem;
    bf16* sAl = smem + 128*SST;
    bf16* sBh = smem + 2*128*SST;
    bf16* sBl = smem + 3*128*SST;

    const int tid = threadIdx.x, warp = tid>>5, lane = tid&31;
    const int wm = warp>>2, wn = warp&3;
    const int m0 = blockIdx.y*128, n0 = blockIdx.x*128, z = blockIdx.z;
    A += (long long)z*szA; B += (long long)z*szB;

    const uint32_t bAh = smem_u32(sAh), bAl = smem_u32(sAl);
    const uint32_t bBh = smem_u32(sBh), bBl = smem_u32(sBl);

    float acc[2][4][4];
    #pragma unroll
    for (int i=0;i<2;i++)
        #pragma unroll
        for (int j=0;j<4;j++)
            #pragma unroll
            for (int t=0;t<4;t++) acc[i][j][t] = 0.f;

    int fr[4], fc[4];
    #pragma unroll
    for (int i=0;i<4;i++){ int id = tid + (i<<9); fr[i]=id>>4; fc[i]=(id&15)<<2; }

    float2 rsv[4];
    if (MODE==1){
        #pragma unroll
        for (int i=0;i<4;i++) rsv[i] = __ldg(&rs[(long long)z*1024 + m0 + fr[i]]);
    }

    float4 pA[4], pB[4];
    #pragma unroll
    for (int i=0;i<4;i++){
        pA[i] = *(const float4*)(A + (long long)(m0+fr[i])*K + fc[i]);
        pB[i] = *(const float4*)(B + (long long)(n0+fr[i])*K + fc[i]);
    }

    const int nch = K >> 6;
    for (int kc=0; kc<nch; kc++){
        #pragma unroll
        for (int i=0;i<4;i++){
            float4 ra = pA[i];
            if (MODE==1){
                ra.x = __expf(ra.x - rsv[i].x)*rsv[i].y;
                ra.y = __expf(ra.y - rsv[i].x)*rsv[i].y;
                ra.z = __expf(ra.z - rsv[i].x)*rsv[i].y;
                ra.w = __expf(ra.w - rsv[i].x)*rsv[i].y;
            }
            uint2 h, l;
            split4(ra, h, l);
            *(uint2*)(sAh + fr[i]*SST + fc[i]) = h;
            *(uint2*)(sAl + fr[i]*SST + fc[i]) = l;
            split4(pB[i], h, l);
            *(uint2*)(sBh + fr[i]*SST + fc[i]) = h;
            *(uint2*)(sBl + fr[i]*SST + fc[i]) = l;
        }
        __syncthreads();

        if (kc+1 < nch){
            const int k0 = (kc+1)<<6;
            #pragma unroll
            for (int i=0;i<4;i++){
                pA[i] = *(const float4*)(A + (long long)(m0+fr[i])*K + k0 + fc[i]);
                pB[i] = *(const float4*)(B + (long long)(n0+fr[i])*K + k0 + fc[i]);
            }
        }

        #pragma unroll
        for (int k16=0; k16<4; k16++){
            const uint32_t akoff = k16*32 + ((lane>>4)<<4);
            const uint32_t bkoff = k16*32 + (((lane>>3)&1)<<4);
            const uint32_t arow  = (wm*32 + (lane&15)) * (SST*2);
            const uint32_t brow  = (wn*32 + ((lane>>4)<<3) + (lane&7)) * (SST*2);

            uint32_t Ah[2][4], Al[2][4], Bh[2][4], Bl[2][4];
            #pragma unroll
            for (int mi=0;mi<2;mi++){
                ldsm4(bAh + arow + mi*16*(SST*2) + akoff, Ah[mi]);
                ldsm4(bAl + arow + mi*16*(SST*2) + akoff, Al[mi]);
            }
            #pragma unroll
            for (int bi=0;bi<2;bi++){
                ldsm4(bBh + brow + bi*16*(SST*2) + bkoff, Bh[bi]);
                ldsm4(bBl + brow + bi*16*(SST*2) + bkoff, Bl[bi]);
            }
            #pragma unroll
            for (int mi=0;mi<2;mi++)
                #pragma unroll
                for (int ni=0;ni<4;ni++){
                    mma16816(acc[mi][ni], Ah[mi], &Bh[ni>>1][(ni&1)*2]);
                    mma16816(acc[mi][ni], Ah[mi], &Bl[ni>>1][(ni&1)*2]);
                    mma16816(acc[mi][ni], Al[mi], &Bh[ni>>1][(ni&1)*2]);
                }
        }
        __syncthreads();
    }

    C += (long long)z*szC;

    if (MODE==0){
        // masked scaled scores + per-(row, tile) softmax partials
        float* smr = (float*)smem;   // [128][8]: [r*8+wn]=max, [r*8+4+wn]=sum
        const int mt = *mtp;
        const long long mbase = (long long)z * 1024LL * N;
        #pragma unroll
        for (int mi=0;mi<2;mi++)
            #pragma unroll
            for (int half=0; half<2; half++){
                int rl = wm*32 + mi*16 + (lane>>2) + half*8;
                long long row = m0 + rl;
                float vals[8]; float rm = -1e30f;
                #pragma unroll
                for (int ni=0;ni<4;ni++)
                    #pragma unroll
                    for (int e=0;e<2;e++){
                        int c = n0 + wn*32 + ni*8 + (lane&3)*2 + e;
                        float v = acc[mi][ni][half*2+e]*alpha;
                        if (mchk(mask, mt, mbase + row*(long long)N + c)) v = -1e30f;
                        vals[ni*2+e] = v;
                        rm = fmaxf(rm, v);
                    }
                float rsum = 0.f;
                #pragma unroll
                for (int j=0;j<8;j++) rsum += __expf(vals[j]-rm);
                #pragma unroll
                for (int ni=0;ni<4;ni++)
                    *(float2*)(C + row*(long long)N + n0 + wn*32 + ni*8 + (lane&3)*2)
                        = make_float2(vals[ni*2], vals[ni*2+1]);
                #pragma unroll
                for (int d=1; d<4; d<<=1){
                    float om = __shfl_xor_sync(0xffffffffu, rm, d);
                    float os = __shfl_xor_sync(0xffffffffu, rsum, d);
                    float nm = fmaxf(rm, om);
                    rsum = rsum*__expf(rm-nm) + os*__expf(om-nm);
                    rm = nm;
                }
                if ((lane&3)==0){ smr[rl*8+wn] = rm; smr[rl*8+4+wn] = rsum; }
            }
        __syncthreads();
        if (tid < 128){
            float m = -1e30f;
            #pragma unroll
            for (int w=0;w<4;w++) m = fmaxf(m, smr[tid*8+w]);
            float ssum = 0.f;
            #pragma unroll
            for (int w=0;w<4;w++) ssum += smr[tid*8+4+w]*__expf(smr[tid*8+w]-m);
            stats[((long long)z*1024 + m0 + tid)*16 + blockIdx.x] = make_float2(m, ssum);
        }
    } else {
        const int mrow = m0 + wm*32 + (lane>>2);
        const int ncol = n0 + wn*32 + (lane&3)*2;
        #pragma unroll
        for (int mi=0;mi<2;mi++)
            #pragma unroll
            for (int ni=0;ni<4;ni++)
                #pragma unroll
                for (int half=0; half<2; half++){
                    int r = mrow + mi*16 + half*8;
                    int c = ncol + ni*8;
                    float2 v;
                    v.x = acc[mi][ni][half*2+0]*alpha;
                    v.y = acc[mi][ni][half*2+1]*alpha;
                    *(float2*)(C + (long long)r*N + c) = v;
                }
    }
}

// ---------------- merge per-tile stats -> per-row (max, 1/l) ----------------
__global__ void merge_stats(const float2* __restrict__ stats,
                            float2* __restrict__ rs, int T)
{
    int r = blockIdx.x*256 + threadIdx.x;   // 16384 rows
    const float2* p = stats + (long long)r*16;
    float m = -1e30f;
    for (int t=0;t<T;t++) m = fmaxf(m, p[t].x);
    float l = 0.f;
    for (int t=0;t<T;t++) l += p[t].y*__expf(p[t].x - m);
    float inv = (m <= -1e29f || l <= 0.f) ? 0.f : 1.f/l;
    rs[r] = make_float2(m, inv);
}

// ---------------- transpose: out[z][c][r] = in[z][r][c] ----------------
__global__ void transpose_k(const float* __restrict__ in, float* __restrict__ out,
                            int R, int C, long long sIn, long long sOut)
{
    __shared__ float t[32][33];
    const int z = blockIdx.z;
    in += (long long)z*sIn; out += (long long)z*sOut;
    int r0 = blockIdx.y*32, c0 = blockIdx.x*32;
    #pragma unroll
    for (int j=0;j<4;j++)
        t[threadIdx.y+j*8][threadIdx.x] = in[(long long)(r0+threadIdx.y+j*8)*C + c0+threadIdx.x];
    __syncthreads();
    #pragma unroll
    for (int j=0;j<4;j++)
        out[(long long)(c0+threadIdx.y+j*8)*R + r0+threadIdx.x] = t[threadIdx.x][threadIdx.y+j*8];
}

// ---------------- mask dtype detection (0=int32,1=uint8,2=float32) ----------
__global__ void detect_mask_kernel(const uint32_t* __restrict__ m, int nw, int* __restrict__ f)
{
    __shared__ int wg, bb;
    if (threadIdx.x==0){ wg=0; bb=0; }
    __syncthreads();
    int lw=0, lb=0;
    for (int i=threadIdx.x;i<nw;i+=blockDim.x){
        uint32_t w = m[i];
        if (w>1u) lw=1;
        #pragma unroll
        for (int b=0;b<4;b++) if (((w>>(8*b))&0xFFu)>1u) lb=1;
    }
    if (lw) atomicOr(&wg,1);
    if (lb) atomicOr(&bb,1);
    __syncthreads();
    if (threadIdx.x==0) *f = (!wg)?0:((!bb)?1:2);
}

// ---------------- LN + residual / final add ----------------
__device__ __forceinline__ float blk_red(float v){
    __shared__ float sh[256];
    int t = threadIdx.x; sh[t]=v; __syncthreads();
    #pragma unroll
    for (int s=128;s>0;s>>=1){ if (t<s) sh[t]=sh[t]+sh[t+s]; __syncthreads(); }
    float r = sh[0]; __syncthreads(); return r;
}

__global__ __launch_bounds__(256)
void ln_res_kernel(const float* __restrict__ x, const float* __restrict__ res,
                   const float* __restrict__ gm, const float* __restrict__ bt,
                   float* __restrict__ out)
{
    const long long row = blockIdx.x;
    const int t = threadIdx.x;
    float v = x[row*HDIM+t];
    float mu = blk_red(v)*(1.f/HDIM);
    float d = v-mu;
    float var = blk_red(d*d)*(1.f/HDIM);
    out[row*HDIM+t] = d*rsqrtf(var+1e-5f)*gm[t]+bt[t] + res[row*HDIM+t];
}

__global__ void add_kernel(const float* __restrict__ a, const float* __restrict__ b,
                           float* __restrict__ o, long long n)
{
    long long i = (long long)blockIdx.x*blockDim.x + threadIdx.x;
    if (i<n) o[i] = a[i]+b[i];
}

// ---------------- host orchestration ----------------
static void run_layer(const float* x1, const float* x2, const void* mask,
                      const int* mt, int Nk,
                      const float* wqT, const float* bq_l,
                      const float* wkT, const float* bk_l,
                      const float* wvT, const float* bv_l,
                      const float* gm, const float* bt, float* xout,
                      float* q, float* k, float* v, float* vt, float* s,
                      float* at, float2* stats, float2* rsb)
{
    const int Bb=16, Nq=1024;
    proj_fused<<<Bb*Nq/128, 512, PSMEM>>>(x1, wqT, bq_l, q);
    proj_fused<<<Bb*Nk/128, 512, PSMEM>>>(x2, wkT, bk_l, k);
    proj_fused<<<Bb*Nk/128, 512, PSMEM>>>(x2, wvT, bv_l, v);
    {
        dim3 g(HDIM/32, Nk/32, Bb);
        transpose_k<<<g, dim3(32,8)>>>(v, vt, Nk, HDIM, (long long)Nk*HDIM, (long long)Nk*HDIM);
    }
    // QK: masked scaled scores + softmax partials
    {
        dim3 g(Nk/128, Nq/128, Bb);
        gemm_attn<0><<<g, 512, GSMEM>>>(q, k, s, Nk, HDIM,
            (long long)Nq*HDIM, (long long)Nk*HDIM, (long long)Nq*Nk, 0.0625f,
            mask, mt, stats, nullptr);
    }
    merge_stats<<<64, 256>>>(stats, rsb, Nk/128);
    // SV: softmax applied on A load
    {
        dim3 g(HDIM/128, Nq/128, Bb);
        gemm_attn<1><<<g, 512, GSMEM>>>(s, vt, at, HDIM, Nk,
            (long long)Nq*Nk, (long long)Nk*HDIM, (long long)Nq*HDIM, 1.f,
            nullptr, nullptr, nullptr, rsb);
    }
    ln_res_kernel<<<Bb*Nq, 256>>>(at, x1, gm, bt, xout);
}

extern "C" void kernel_launch(void* const* d_in, const int* in_sizes, int n_in,
                              void* d_out, int out_size)
{
    const float* future  = (const float*)d_in[0];
    const float* history = (const float*)d_in[1];
    const float* graph   = (const float*)d_in[2];
    const void*  mask_hf = d_in[3];
    const void*  mask_fg = d_in[4];
    const float* Wq = (const float*)d_in[5];
    const float* bq = (const float*)d_in[6];
    const float* Wk = (const float*)d_in[7];
    const float* bk = (const float*)d_in[8];
    const float* Wv = (const float*)d_in[9];
    const float* bv = (const float*)d_in[10];
    const float* gm = (const float*)d_in[11];
    const float* bt = (const float*)d_in[12];
    float* out = (float*)d_out;

    cudaFuncSetAttribute(gemm_attn<0>, cudaFuncAttributeMaxDynamicSharedMemorySize, GSMEM);
    cudaFuncSetAttribute(gemm_attn<1>, cudaFuncAttributeMaxDynamicSharedMemorySize, GSMEM);
    cudaFuncSetAttribute(proj_fused,   cudaFuncAttributeMaxDynamicSharedMemorySize, PSMEM);

    float *q,*k,*v,*vt,*s,*at,*xA,*xB,*wqT,*wkT,*wvT;
    float2 *stats,*rsb;
    int *mhf,*mfg;
    cudaGetSymbolAddress((void**)&q,g_q);     cudaGetSymbolAddress((void**)&k,g_k);
    cudaGetSymbolAddress((void**)&v,g_v);     cudaGetSymbolAddress((void**)&vt,g_vt);
    cudaGetSymbolAddress((void**)&s,g_s);     cudaGetSymbolAddress((void**)&at,g_at);
    cudaGetSymbolAddress((void**)&xA,g_xA);   cudaGetSymbolAddress((void**)&xB,g_xB);
    cudaGetSymbolAddress((void**)&wqT,g_wqT); cudaGetSymbolAddress((void**)&wkT,g_wkT);
    cudaGetSymbolAddress((void**)&wvT,g_wvT);
    cudaGetSymbolAddress((void**)&stats,g_stats);
    cudaGetSymbolAddress((void**)&rsb,g_rs);
    cudaGetSymbolAddress((void**)&mhf,g_mt_hf); cudaGetSymbolAddress((void**)&mfg,g_mt_fg);

    {
        int nh = in_sizes[3]/4; if (nh>65536) nh=65536;
        int ng = in_sizes[4]/4; if (ng>65536) ng=65536;
        detect_mask_kernel<<<1,256>>>((const uint32_t*)mask_hf, nh, mhf);
        detect_mask_kernel<<<1,256>>>((const uint32_t*)mask_fg, ng, mfg);
    }
    {
        dim3 g(8,8,12), b(32,8);
        transpose_k<<<g,b>>>(Wq, wqT, 256,256, 65536,65536);
        transpose_k<<<g,b>>>(Wk, wkT, 256,256, 65536,65536);
        transpose_k<<<g,b>>>(Wv, wvT, 256,256, 65536,65536);
    }

    const long long WL = 3LL*65536, BL = 3LL*256;
    run_layer(future, history, mask_hf, mhf, 1024,
              wqT+0*WL, bq+0*BL, wkT+0*WL, bk+0*BL, wvT+0*WL, bv+0*BL,
              gm+0*256, bt+0*256, xA, q,k,v,vt,s,at,stats,rsb);
    run_layer(xA, history, mask_hf, mhf, 1024,
              wqT+1*WL, bq+1*BL, wkT+1*WL, bk+1*BL, wvT+1*WL, bv+1*BL,
              gm+1*256, bt+1*256, xB, q,k,v,vt,s,at,stats,rsb);
    run_layer(xB, graph, mask_fg, mfg, 2048,
              wqT+2*WL, bq+2*BL, wkT+2*WL, bk+2*BL, wvT+2*WL, bv+2*BL,
              gm+2*256, bt+2*256, xA, q,k,v,vt,s,at,stats,rsb);
    run_layer(xA, graph, mask_fg, mfg, 2048,
              wqT+3*WL, bq+3*BL, wkT+3*WL, bk+3*BL, wvT+3*WL, bv+3*BL,
              gm+3*256, bt+3*256, xB, q,k,v,vt,s,at,stats,rsb);

    long long n = (long long)out_size;
    add_kernel<<<(unsigned)((n+255)/256),256>>>(future, xB, out, n);
}

// round 10
// speedup vs baseline: 2.4879x; 1.0004x over previous
// bf16-split mma.sync + fused proj chains + fused softmax-stats attention.
#include <cuda_runtime.h>
#include <cuda_bf16.h>
#include <cstdint>
#include <math.h>

#define HDIM 256
typedef __nv_bfloat16 bf16;

// ---------------- scratch (device globals) ----------------
__device__ float g_q [16*1024*256];
__device__ float g_k [16*2048*256];
__device__ float g_v [16*2048*256];
__device__ float g_vt[16*2048*256];
__device__ float g_s [16LL*1024*2048];
__device__ float g_at[16*1024*256];
__device__ float g_xA[16*1024*256];
__device__ float g_xB[16*1024*256];
__device__ float g_wqT[12*65536];
__device__ float g_wkT[12*65536];
__device__ float g_wvT[12*65536];
__device__ float2 g_stats[16*1024*16];   // per-(row, n-tile) partial (max, sum)
__device__ float2 g_rs[16*1024];         // per-row (max, 1/l)
__device__ int g_mt_hf, g_mt_fg;

// ---------------- helpers ----------------
__device__ __forceinline__ uint32_t smem_u32(const void* p){
    uint32_t a; asm("{ .reg .u64 t; cvta.to.shared.u64 t, %1; cvt.u32.u64 %0, t; }":"=r"(a):"l"(p)); return a;
}
__device__ __forceinline__ void ldsm4(uint32_t addr, uint32_t* r){
    asm volatile("ldmatrix.sync.aligned.m8n8.x4.shared.b16 {%0,%1,%2,%3}, [%4];"
        : "=r"(r[0]),"=r"(r[1]),"=r"(r[2]),"=r"(r[3]) : "r"(addr));
}
__device__ __forceinline__ void mma16816(float* c, const uint32_t* a, const uint32_t* b){
    asm volatile("mma.sync.aligned.m16n8k16.row.col.f32.bf16.bf16.f32 "
        "{%0,%1,%2,%3},{%4,%5,%6,%7},{%8,%9},{%0,%1,%2,%3};"
        : "+f"(c[0]),"+f"(c[1]),"+f"(c[2]),"+f"(c[3])
        : "r"(a[0]),"r"(a[1]),"r"(a[2]),"r"(a[3]),"r"(b[0]),"r"(b[1]));
}
__device__ __forceinline__ void split4(float4 v, uint2& h, uint2& l){
    bf16 hb[4], lb[4];
    float xs[4] = {v.x, v.y, v.z, v.w};
    #pragma unroll
    for (int i=0;i<4;i++){ hb[i]=__float2bfloat16(xs[i]); lb[i]=__float2bfloat16(xs[i]-__bfloat162float(hb[i])); }
    h = *(uint2*)hb; l = *(uint2*)lb;
}
__device__ __forceinline__ bool mchk(const void* m, int mt, long long idx){
    if (mt==0) return ((const int*)m)[idx]!=0;
    if (mt==1) return ((const uint8_t*)m)[idx]!=0;
    return ((const float*)m)[idx]!=0.f;
}

// ============================================================================
// Fused 3-stage projection (unchanged from R8).
// ============================================================================
#define ASST 264
#define BSST 72
#define PSMEM ((2*128*ASST + 2*256*BSST)*2)

__global__ __launch_bounds__(512, 1)
void proj_fused(const float* __restrict__ X, const float* __restrict__ WT,
                const float* __restrict__ bias, float* __restrict__ Out)
{
    extern __shared__ bf16 sm[];
    bf16* sAh = sm;
    bf16* sAl = sm + 128*ASST;
    bf16* sBh = sm + 2*128*ASST;
    bf16* sBl = sm + 2*128*ASST + 256*BSST;

    const int tid = threadIdx.x, warp = tid>>5, lane = tid&31;
    const int wm = warp>>2, wn = warp&3;
    const long long m0 = (long long)blockIdx.x * 128;

    const uint32_t bAh = smem_u32(sAh), bAl = smem_u32(sAl);
    const uint32_t bBh = smem_u32(sBh), bBl = smem_u32(sBl);

    #pragma unroll
    for (int i=0;i<16;i++){
        int id = tid + (i<<9);
        int r = id>>6, c4 = (id&63)<<2;
        uint2 h, l;
        split4(*(const float4*)(X + (m0+r)*256 + c4), h, l);
        *(uint2*)(sAh + r*ASST + c4) = h;
        *(uint2*)(sAl + r*ASST + c4) = l;
    }

    float acc[2][8][4];

    #pragma unroll 1
    for (int s=0; s<3; s++){
        const float* W  = WT + s*65536;
        const float* bp = bias + s*256;
        #pragma unroll
        for (int mi=0;mi<2;mi++)
            #pragma unroll
            for (int ni=0;ni<8;ni++)
                #pragma unroll
                for (int t=0;t<4;t++) acc[mi][ni][t] = 0.f;

        #pragma unroll 1
        for (int kc=0; kc<4; kc++){
            const int k0 = kc<<6;
            #pragma unroll
            for (int i=0;i<8;i++){
                int id = tid + (i<<9);
                int r = id>>4, c4 = (id&15)<<2;
                uint2 h, l;
                split4(*(const float4*)(W + r*256 + k0 + c4), h, l);
                *(uint2*)(sBh + r*BSST + c4) = h;
                *(uint2*)(sBl + r*BSST + c4) = l;
            }
            __syncthreads();

            #pragma unroll
            for (int k16=0; k16<4; k16++){
                const uint32_t acol = (k0 + k16*16)*2 + ((lane>>4)<<4);
                const uint32_t arow = (wm*32 + (lane&15)) * (ASST*2);
                uint32_t Ah[2][4], Al[2][4];
                #pragma unroll
                for (int mi=0;mi<2;mi++){
                    ldsm4(bAh + arow + mi*16*(ASST*2) + acol, Ah[mi]);
                    ldsm4(bAl + arow + mi*16*(ASST*2) + acol, Al[mi]);
                }
                const uint32_t bcol = k16*32 + (((lane>>3)&1)<<4);
                #pragma unroll
                for (int bi=0;bi<4;bi++){
                    const uint32_t brow = (wn*64 + bi*16 + ((lane>>4)<<3) + (lane&7)) * (BSST*2);
                    uint32_t Bh[4], Bl[4];
                    ldsm4(bBh + brow + bcol, Bh);
                    ldsm4(bBl + brow + bcol, Bl);
                    #pragma unroll
                    for (int mi=0;mi<2;mi++)
                        #pragma unroll
                        for (int nh=0;nh<2;nh++){
                            int ni = bi*2+nh;
                            mma16816(acc[mi][ni], Ah[mi], &Bh[nh*2]);
                            mma16816(acc[mi][ni], Ah[mi], &Bl[nh*2]);
                            mma16816(acc[mi][ni], Al[mi], &Bh[nh*2]);
                        }
                }
            }
            __syncthreads();
        }

        const int rbase = wm*32 + (lane>>2);
        const int cbase = wn*64 + (lane&3)*2;
        if (s < 2){
            #pragma unroll
            for (int mi=0;mi<2;mi++)
                #pragma unroll
                for (int ni=0;ni<8;ni++)
                    #pragma unroll
                    for (int half=0; half<2; half++){
                        int r = rbase + mi*16 + half*8;
                        int c = cbase + ni*8;
                        float v0 = acc[mi][ni][half*2+0] + __ldg(bp+c);
                        float v1 = acc[mi][ni][half*2+1] + __ldg(bp+c+1);
                        bf16 h0 = __float2bfloat16(v0);
                        bf16 h1 = __float2bfloat16(v1);
                        sAh[r*ASST+c]   = h0;
                        sAh[r*ASST+c+1] = h1;
                        sAl[r*ASST+c]   = __float2bfloat16(v0 - __bfloat162float(h0));
                        sAl[r*ASST+c+1] = __float2bfloat16(v1 - __bfloat162float(h1));
                    }
            __syncthreads();
        } else {
            #pragma unroll
            for (int mi=0;mi<2;mi++)
                #pragma unroll
                for (int ni=0;ni<8;ni++)
                    #pragma unroll
                    for (int half=0; half<2; half++){
                        int r = rbase + mi*16 + half*8;
                        int c = cbase + ni*8;
                        float2 v;
                        v.x = acc[mi][ni][half*2+0] + __ldg(bp+c);
                        v.y = acc[mi][ni][half*2+1] + __ldg(bp+c+1);
                        *(float2*)(Out + (m0+r)*256 + c) = v;
                    }
        }
    }
}

// ============================================================================
// Attention GEMMs. MODE 0 (QK): C = masked(alpha*A@B^T), epilogue emits
// per-(row,tile) softmax partials (max, sum) to stats. MODE 1 (SV): A values
// transformed a = exp(s - m)*invl on load (softmax applied in-GEMM).
// CTA 128x128, K-chunk 64, 512 thr, register prefetch (same core as R7/R8).
// ============================================================================
#define SST 72
#define GSMEM (4*128*SST*2)

template<int MODE>
__global__ __launch_bounds__(512)
void gemm_attn(const float* __restrict__ A, const float* __restrict__ B,
               float* __restrict__ C, int N, int K,
               long long szA, long long szB, long long szC, float alpha,
               const void* __restrict__ mask, const int* __restrict__ mtp,
               float2* __restrict__ stats, const float2* __restrict__ rs)
{
    extern __shared__ bf16 smem[];
    bf16* sAh = smem;
    bf16* sAl = smem + 128*SST;
    bf16* sBh = smem + 2*128*SST;
    bf16* sBl = smem + 3*128*SST;

    const int tid = threadIdx.x, warp = tid>>5, lane = tid&31;
    const int wm = warp>>2, wn = warp&3;
    const int m0 = blockIdx.y*128, n0 = blockIdx.x*128, z = blockIdx.z;
    A += (long long)z*szA; B += (long long)z*szB;

    const uint32_t bAh = smem_u32(sAh), bAl = smem_u32(sAl);
    const uint32_t bBh = smem_u32(sBh), bBl = smem_u32(sBl);

    float acc[2][4][4];
    #pragma unroll
    for (int i=0;i<2;i++)
        #pragma unroll
        for (int j=0;j<4;j++)
            #pragma unroll
            for (int t=0;t<4;t++) acc[i][j][t] = 0.f;

    int fr[4], fc[4];
    #pragma unroll
    for (int i=0;i<4;i++){ int id = tid + (i<<9); fr[i]=id>>4; fc[i]=(id&15)<<2; }

    float2 rsv[4];
    if (MODE==1){
        #pragma unroll
        for (int i=0;i<4;i++) rsv[i] = __ldg(&rs[(long long)z*1024 + m0 + fr[i]]);
    }

    float4 pA[4], pB[4];
    #pragma unroll
    for (int i=0;i<4;i++){
        pA[i] = *(const float4*)(A + (long long)(m0+fr[i])*K + fc[i]);
        pB[i] = *(const float4*)(B + (long long)(n0+fr[i])*K + fc[i]);
    }

    const int nch = K >> 6;
    for (int kc=0; kc<nch; kc++){
        #pragma unroll
        for (int i=0;i<4;i++){
            float4 ra = pA[i];
            if (MODE==1){
                ra.x = __expf(ra.x - rsv[i].x)*rsv[i].y;
                ra.y = __expf(ra.y - rsv[i].x)*rsv[i].y;
                ra.z = __expf(ra.z - rsv[i].x)*rsv[i].y;
                ra.w = __expf(ra.w - rsv[i].x)*rsv[i].y;
            }
            uint2 h, l;
            split4(ra, h, l);
            *(uint2*)(sAh + fr[i]*SST + fc[i]) = h;
            *(uint2*)(sAl + fr[i]*SST + fc[i]) = l;
            split4(pB[i], h, l);
            *(uint2*)(sBh + fr[i]*SST + fc[i]) = h;
            *(uint2*)(sBl + fr[i]*SST + fc[i]) = l;
        }
        __syncthreads();

        if (kc+1 < nch){
            const int k0 = (kc+1)<<6;
            #pragma unroll
            for (int i=0;i<4;i++){
                pA[i] = *(const float4*)(A + (long long)(m0+fr[i])*K + k0 + fc[i]);
                pB[i] = *(const float4*)(B + (long long)(n0+fr[i])*K + k0 + fc[i]);
            }
        }

        #pragma unroll
        for (int k16=0; k16<4; k16++){
            const uint32_t akoff = k16*32 + ((lane>>4)<<4);
            const uint32_t bkoff = k16*32 + (((lane>>3)&1)<<4);
            const uint32_t arow  = (wm*32 + (lane&15)) * (SST*2);
            const uint32_t brow  = (wn*32 + ((lane>>4)<<3) + (lane&7)) * (SST*2);

            uint32_t Ah[2][4], Al[2][4], Bh[2][4], Bl[2][4];
            #pragma unroll
            for (int mi=0;mi<2;mi++){
                ldsm4(bAh + arow + mi*16*(SST*2) + akoff, Ah[mi]);
                ldsm4(bAl + arow + mi*16*(SST*2) + akoff, Al[mi]);
            }
            #pragma unroll
            for (int bi=0;bi<2;bi++){
                ldsm4(bBh + brow + bi*16*(SST*2) + bkoff, Bh[bi]);
                ldsm4(bBl + brow + bi*16*(SST*2) + bkoff, Bl[bi]);
            }
            #pragma unroll
            for (int mi=0;mi<2;mi++)
                #pragma unroll
                for (int ni=0;ni<4;ni++){
                    mma16816(acc[mi][ni], Ah[mi], &Bh[ni>>1][(ni&1)*2]);
                    mma16816(acc[mi][ni], Ah[mi], &Bl[ni>>1][(ni&1)*2]);
                    mma16816(acc[mi][ni], Al[mi], &Bh[ni>>1][(ni&1)*2]);
                }
        }
        __syncthreads();
    }

    C += (long long)z*szC;

    if (MODE==0){
        // masked scaled scores + per-(row, tile) softmax partials
        float* smr = (float*)smem;   // [128][8]: [r*8+wn]=max, [r*8+4+wn]=sum
        const int mt = *mtp;
        const long long mbase = (long long)z * 1024LL * N;
        #pragma unroll
        for (int mi=0;mi<2;mi++)
            #pragma unroll
            for (int half=0; half<2; half++){
                int rl = wm*32 + mi*16 + (lane>>2) + half*8;
                long long row = m0 + rl;
                float vals[8]; float rm = -1e30f;
                #pragma unroll
                for (int ni=0;ni<4;ni++)
                    #pragma unroll
                    for (int e=0;e<2;e++){
                        int c = n0 + wn*32 + ni*8 + (lane&3)*2 + e;
                        float v = acc[mi][ni][half*2+e]*alpha;
                        if (mchk(mask, mt, mbase + row*(long long)N + c)) v = -1e30f;
                        vals[ni*2+e] = v;
                        rm = fmaxf(rm, v);
                    }
                float rsum = 0.f;
                #pragma unroll
                for (int j=0;j<8;j++) rsum += __expf(vals[j]-rm);
                #pragma unroll
                for (int ni=0;ni<4;ni++)
                    *(float2*)(C + row*(long long)N + n0 + wn*32 + ni*8 + (lane&3)*2)
                        = make_float2(vals[ni*2], vals[ni*2+1]);
                #pragma unroll
                for (int d=1; d<4; d<<=1){
                    float om = __shfl_xor_sync(0xffffffffu, rm, d);
                    float os = __shfl_xor_sync(0xffffffffu, rsum, d);
                    float nm = fmaxf(rm, om);
                    rsum = rsum*__expf(rm-nm) + os*__expf(om-nm);
                    rm = nm;
                }
                if ((lane&3)==0){ smr[rl*8+wn] = rm; smr[rl*8+4+wn] = rsum; }
            }
        __syncthreads();
        if (tid < 128){
            float m = -1e30f;
            #pragma unroll
            for (int w=0;w<4;w++) m = fmaxf(m, smr[tid*8+w]);
            float ssum = 0.f;
            #pragma unroll
            for (int w=0;w<4;w++) ssum += smr[tid*8+4+w]*__expf(smr[tid*8+w]-m);
            stats[((long long)z*1024 + m0 + tid)*16 + blockIdx.x] = make_float2(m, ssum);
        }
    } else {
        const int mrow = m0 + wm*32 + (lane>>2);
        const int ncol = n0 + wn*32 + (lane&3)*2;
        #pragma unroll
        for (int mi=0;mi<2;mi++)
            #pragma unroll
            for (int ni=0;ni<4;ni++)
                #pragma unroll
                for (int half=0; half<2; half++){
                    int r = mrow + mi*16 + half*8;
                    int c = ncol + ni*8;
                    float2 v;
                    v.x = acc[mi][ni][half*2+0]*alpha;
                    v.y = acc[mi][ni][half*2+1]*alpha;
                    *(float2*)(C + (long long)r*N + c) = v;
                }
    }
}

// ---------------- merge per-tile stats -> per-row (max, 1/l) ----------------
__global__ void merge_stats(const float2* __restrict__ stats,
                            float2* __restrict__ rs, int T)
{
    int r = blockIdx.x*256 + threadIdx.x;   // 16384 rows
    const float2* p = stats + (long long)r*16;
    float m = -1e30f;
    for (int t=0;t<T;t++) m = fmaxf(m, p[t].x);
    float l = 0.f;
    for (int t=0;t<T;t++) l += p[t].y*__expf(p[t].x - m);
    float inv = (m <= -1e29f || l <= 0.f) ? 0.f : 1.f/l;
    rs[r] = make_float2(m, inv);
}

// ---------------- transpose: out[z][c][r] = in[z][r][c] ----------------
__global__ void transpose_k(const float* __restrict__ in, float* __restrict__ out,
                            int R, int C, long long sIn, long long sOut)
{
    __shared__ float t[32][33];
    const int z = blockIdx.z;
    in += (long long)z*sIn; out += (long long)z*sOut;
    int r0 = blockIdx.y*32, c0 = blockIdx.x*32;
    #pragma unroll
    for (int j=0;j<4;j++)
        t[threadIdx.y+j*8][threadIdx.x] = in[(long long)(r0+threadIdx.y+j*8)*C + c0+threadIdx.x];
    __syncthreads();
    #pragma unroll
    for (int j=0;j<4;j++)
        out[(long long)(c0+threadIdx.y+j*8)*R + r0+threadIdx.x] = t[threadIdx.x][threadIdx.y+j*8];
}

// ---------------- mask dtype detection (0=int32,1=uint8,2=float32) ----------
__global__ void detect_mask_kernel(const uint32_t* __restrict__ m, int nw, int* __restrict__ f)
{
    __shared__ int wg, bb;
    if (threadIdx.x==0){ wg=0; bb=0; }
    __syncthreads();
    int lw=0, lb=0;
    for (int i=threadIdx.x;i<nw;i+=blockDim.x){
        uint32_t w = m[i];
        if (w>1u) lw=1;
        #pragma unroll
        for (int b=0;b<4;b++) if (((w>>(8*b))&0xFFu)>1u) lb=1;
    }
    if (lw) atomicOr(&wg,1);
    if (lb) atomicOr(&bb,1);
    __syncthreads();
    if (threadIdx.x==0) *f = (!wg)?0:((!bb)?1:2);
}

// ---------------- LN + residual / final add ----------------
__device__ __forceinline__ float blk_red(float v){
    __shared__ float sh[256];
    int t = threadIdx.x; sh[t]=v; __syncthreads();
    #pragma unroll
    for (int s=128;s>0;s>>=1){ if (t<s) sh[t]=sh[t]+sh[t+s]; __syncthreads(); }
    float r = sh[0]; __syncthreads(); return r;
}

__global__ __launch_bounds__(256)
void ln_res_kernel(const float* __restrict__ x, const float* __restrict__ res,
                   const float* __restrict__ gm, const float* __restrict__ bt,
                   float* __restrict__ out)
{
    const long long row = blockIdx.x;
    const int t = threadIdx.x;
    float v = x[row*HDIM+t];
    float mu = blk_red(v)*(1.f/HDIM);
    float d = v-mu;
    float var = blk_red(d*d)*(1.f/HDIM);
    out[row*HDIM+t] = d*rsqrtf(var+1e-5f)*gm[t]+bt[t] + res[row*HDIM+t];
}

__global__ void add_kernel(const float* __restrict__ a, const float* __restrict__ b,
                           float* __restrict__ o, long long n)
{
    long long i = (long long)blockIdx.x*blockDim.x + threadIdx.x;
    if (i<n) o[i] = a[i]+b[i];
}

// ---------------- host orchestration ----------------
static void run_layer(const float* x1, const float* x2, const void* mask,
                      const int* mt, int Nk,
                      const float* wqT, const float* bq_l,
                      const float* wkT, const float* bk_l,
                      const float* wvT, const float* bv_l,
                      const float* gm, const float* bt, float* xout,
                      float* q, float* k, float* v, float* vt, float* s,
                      float* at, float2* stats, float2* rsb)
{
    const int Bb=16, Nq=1024;
    proj_fused<<<Bb*Nq/128, 512, PSMEM>>>(x1, wqT, bq_l, q);
    proj_fused<<<Bb*Nk/128, 512, PSMEM>>>(x2, wkT, bk_l, k);
    proj_fused<<<Bb*Nk/128, 512, PSMEM>>>(x2, wvT, bv_l, v);
    {
        dim3 g(HDIM/32, Nk/32, Bb);
        transpose_k<<<g, dim3(32,8)>>>(v, vt, Nk, HDIM, (long long)Nk*HDIM, (long long)Nk*HDIM);
    }
    // QK: masked scaled scores + softmax partials
    {
        dim3 g(Nk/128, Nq/128, Bb);
        gemm_attn<0><<<g, 512, GSMEM>>>(q, k, s, Nk, HDIM,
            (long long)Nq*HDIM, (long long)Nk*HDIM, (long long)Nq*Nk, 0.0625f,
            mask, mt, stats, nullptr);
    }
    merge_stats<<<64, 256>>>(stats, rsb, Nk/128);
    // SV: softmax applied on A load
    {
        dim3 g(HDIM/128, Nq/128, Bb);
        gemm_attn<1><<<g, 512, GSMEM>>>(s, vt, at, HDIM, Nk,
            (long long)Nq*Nk, (long long)Nk*HDIM, (long long)Nq*HDIM, 1.f,
            nullptr, nullptr, nullptr, rsb);
    }
    ln_res_kernel<<<Bb*Nq, 256>>>(at, x1, gm, bt, xout);
}

extern "C" void kernel_launch(void* const* d_in, const int* in_sizes, int n_in,
                              void* d_out, int out_size)
{
    const float* future  = (const float*)d_in[0];
    const float* history = (const float*)d_in[1];
    const float* graph   = (const float*)d_in[2];
    const void*  mask_hf = d_in[3];
    const void*  mask_fg = d_in[4];
    const float* Wq = (const float*)d_in[5];
    const float* bq = (const float*)d_in[6];
    const float* Wk = (const float*)d_in[7];
    const float* bk = (const float*)d_in[8];
    const float* Wv = (const float*)d_in[9];
    const float* bv = (const float*)d_in[10];
    const float* gm = (const float*)d_in[11];
    const float* bt = (const float*)d_in[12];
    float* out = (float*)d_out;

    cudaFuncSetAttribute(gemm_attn<0>, cudaFuncAttributeMaxDynamicSharedMemorySize, GSMEM);
    cudaFuncSetAttribute(gemm_attn<1>, cudaFuncAttributeMaxDynamicSharedMemorySize, GSMEM);
    cudaFuncSetAttribute(proj_fused,   cudaFuncAttributeMaxDynamicSharedMemorySize, PSMEM);

    float *q,*k,*v,*vt,*s,*at,*xA,*xB,*wqT,*wkT,*wvT;
    float2 *stats,*rsb;
    int *mhf,*mfg;
    cudaGetSymbolAddress((void**)&q,g_q);     cudaGetSymbolAddress((void**)&k,g_k);
    cudaGetSymbolAddress((void**)&v,g_v);     cudaGetSymbolAddress((void**)&vt,g_vt);
    cudaGetSymbolAddress((void**)&s,g_s);     cudaGetSymbolAddress((void**)&at,g_at);
    cudaGetSymbolAddress((void**)&xA,g_xA);   cudaGetSymbolAddress((void**)&xB,g_xB);
    cudaGetSymbolAddress((void**)&wqT,g_wqT); cudaGetSymbolAddress((void**)&wkT,g_wkT);
    cudaGetSymbolAddress((void**)&wvT,g_wvT);
    cudaGetSymbolAddress((void**)&stats,g_stats);
    cudaGetSymbolAddress((void**)&rsb,g_rs);
    cudaGetSymbolAddress((void**)&mhf,g_mt_hf); cudaGetSymbolAddress((void**)&mfg,g_mt_fg);

    {
        int nh = in_sizes[3]/4; if (nh>65536) nh=65536;
        int ng = in_sizes[4]/4; if (ng>65536) ng=65536;
        detect_mask_kernel<<<1,256>>>((const uint32_t*)mask_hf, nh, mhf);
        detect_mask_kernel<<<1,256>>>((const uint32_t*)mask_fg, ng, mfg);
    }
    {
        dim3 g(8,8,12), b(32,8);
        transpose_k<<<g,b>>>(Wq, wqT, 256,256, 65536,65536);
        transpose_k<<<g,b>>>(Wk, wkT, 256,256, 65536,65536);
        transpose_k<<<g,b>>>(Wv, wvT, 256,256, 65536,65536);
    }

    const long long WL = 3LL*65536, BL = 3LL*256;
    run_layer(future, history, mask_hf, mhf, 1024,
              wqT+0*WL, bq+0*BL, wkT+0*WL, bk+0*BL, wvT+0*WL, bv+0*BL,
              gm+0*256, bt+0*256, xA, q,k,v,vt,s,at,stats,rsb);
    run_layer(xA, history, mask_hf, mhf, 1024,
              wqT+1*WL, bq+1*BL, wkT+1*WL, bk+1*BL, wvT+1*WL, bv+1*BL,
              gm+1*256, bt+1*256, xB, q,k,v,vt,s,at,stats,rsb);
    run_layer(xB, graph, mask_fg, mfg, 2048,
              wqT+2*WL, bq+2*BL, wkT+2*WL, bk+2*BL, wvT+2*WL, bv+2*BL,
              gm+2*256, bt+2*256, xA, q,k,v,vt,s,at,stats,rsb);
    run_layer(xA, graph, mask_fg, mfg, 2048,
              wqT+3*WL, bq+3*BL, wkT+3*WL, bk+3*BL, wvT+3*WL, bv+3*BL,
              gm+3*256, bt+3*256, xB, q,k,v,vt,s,at,stats,rsb);

    long long n = (long long)out_size;
    add_kernel<<<(unsigned)((n+255)/256),256>>>(future, xB, out, n);
}